// round 11
// baseline (speedup 1.0000x reference)
#include <cuda_runtime.h>
#include <cuda_fp16.h>
#include <math.h>
#include <stdint.h>

// ---------------- Problem dims ----------------
#define B_      8
#define LQ_     512
#define LK_     256
#define DM_     512
#define DI_     1024
#define DS_     16
#define DTR_    32
#define NBLK_   4
#define NHEAD_  4
#define DH_     128
#define NOUT_   6

#define ROWS_Q  (B_*LQ_)   // 4096
#define ROWS_K  (B_*LK_)   // 2048

// ---------------- Scratch (static device globals; no allocation) ----------------
__device__ float g_x   [ROWS_Q * DM_];
__device__ float g_h   [ROWS_Q * DM_];
__device__ float g_xz  [ROWS_Q * 2 * DI_];
__device__ float g_xc  [ROWS_Q * DI_];
__device__ float g_dbl [ROWS_Q * 64];
__device__ float g_dlt [ROWS_Q * DI_];
__device__ float g_q   [ROWS_Q * DM_];
__device__ float g_k   [ROWS_K * DM_];
__device__ float g_v   [ROWS_K * DM_];
__device__ float g_att [ROWS_Q * DM_];
__device__ __align__(16) __half g_A6   [ROWS_Q * 3 * 1024];   // activation splits
__device__ __align__(16) __half g_Aag  [ROWS_K * 3 * 512];    // agent split (constant input)
__device__ __align__(16) __half g_B6all[25600000];            // all weight splits (~48.4MB used)

// ---------------- fp16 split helpers ----------------
__device__ __forceinline__ uint32_t pack2h(__half a, __half b) {
    return (uint32_t)__half_as_ushort(a) | ((uint32_t)__half_as_ushort(b) << 16);
}
__device__ __forceinline__ void split2(float a, __half& h, __half& m) {
    h = __float2half(a);
    m = __float2half(a - __half2float(h));
}
// pack a pair of A-elements into 3 u32: halves [h0,m0,h0,h1,m1,h1]
__device__ __forceinline__ void packA_pair(float a0, float a1, uint32_t* dst) {
    __half h0, m0, h1, m1;
    split2(a0, h0, m0); split2(a1, h1, m1);
    dst[0] = pack2h(h0, m0);
    dst[1] = pack2h(h0, h1);
    dst[2] = pack2h(m1, h1);
}
__device__ __forceinline__ uint32_t smem_u32(const void* p) {
    uint32_t a;
    asm("{ .reg .u64 t; cvta.to.shared.u64 t, %1; cvt.u32.u64 %0, t; }" : "=r"(a) : "l"(p));
    return a;
}

// ---------------- mma.sync m16n8k16 f16->f32 ----------------
__device__ __forceinline__ void mma16816(float* c, const uint32_t* a, const uint32_t* b) {
    asm volatile("mma.sync.aligned.m16n8k16.row.col.f32.f16.f16.f32 "
        "{%0,%1,%2,%3}, {%4,%5,%6,%7}, {%8,%9}, {%0,%1,%2,%3};"
        : "+f"(c[0]), "+f"(c[1]), "+f"(c[2]), "+f"(c[3])
        : "r"(a[0]), "r"(a[1]), "r"(a[2]), "r"(a[3]), "r"(b[0]), "r"(b[1]));
}

// ================= Pipelined HMMA GEMM (512 threads, 16 warps 4x4) =================
// C[M,N] = A6[M,Keff] * B6[N,Keff]^T.  Keff % 64 == 0 (per split-K slice).
// BK = 64 halves (128B rows, XOR-swizzled). Each warp computes 32 x (BN/4).
template<int BM, int BN, bool ACCUM, bool ATOMIC>
__global__ void __launch_bounds__(512, 1)
mma_gemm_pipe(const __half* __restrict__ A6, const __half* __restrict__ B6,
              const float* __restrict__ bias, float* __restrict__ C, int ldc, int Keff)
{
    constexpr int STAGES = 3;
    constexpr int WM = 32, WN = BN / 4;
    constexpr int MT = WM / 16, NT = WN / 8;     // MT=2
    constexpr int STAGE_BYTES = (BM + BN) * 128;
    extern __shared__ __align__(16) char smem[];
    const uint32_t sbase = smem_u32(smem);

    const int tid = threadIdx.x, lane = tid & 31, w = tid >> 5;   // 16 warps
    const int wm0 = (w >> 2) * WM, wn0 = (w & 3) * WN;
    const int bm = blockIdx.y * BM, bn = blockIdx.x * BN;

    int ktiles = Keff >> 6;
    int kbeg = 0;
    if (ATOMIC) { int kt = ktiles / gridDim.z; kbeg = blockIdx.z * kt; ktiles = kt; }

    auto load_stage = [&](int s, int kt) {
        if (kt >= ktiles) {
            asm volatile("cp.async.commit_group;" ::: "memory");
            return;
        }
        const uint32_t aST = sbase + s * STAGE_BYTES;
        const uint32_t bST = aST + BM * 128;
        const size_t gk = ((size_t)(kbeg + kt)) << 6;
        #pragma unroll
        for (int r = 0; r < BM * 8 / 512; r++) {
            int idx = tid + r * 512;
            int row = idx >> 3, cc = idx & 7;
            uint32_t d = aST + row * 128 + ((cc ^ (row & 7)) << 4);
            const __half* g = A6 + (size_t)(bm + row) * Keff + gk + cc * 8;
            asm volatile("cp.async.cg.shared.global [%0], [%1], 16;" :: "r"(d), "l"(g));
        }
        #pragma unroll
        for (int r = 0; r < BN * 8 / 512; r++) {
            int idx = tid + r * 512;
            int row = idx >> 3, cc = idx & 7;
            uint32_t d = bST + row * 128 + ((cc ^ (row & 7)) << 4);
            const __half* g = B6 + (size_t)(bn + row) * Keff + gk + cc * 8;
            asm volatile("cp.async.cg.shared.global [%0], [%1], 16;" :: "r"(d), "l"(g));
        }
        asm volatile("cp.async.commit_group;" ::: "memory");
    };

    float acc[MT][NT][4];
    #pragma unroll
    for (int i = 0; i < MT; i++)
        #pragma unroll
        for (int j = 0; j < NT; j++)
            #pragma unroll
            for (int q = 0; q < 4; q++) acc[i][j][q] = 0.f;

    #pragma unroll
    for (int s = 0; s < STAGES - 1; s++) load_stage(s, s);

    for (int kt = 0; kt < ktiles; kt++) {
        asm volatile("cp.async.wait_group %0;" :: "n"(STAGES - 2) : "memory");
        __syncthreads();
        const int s = kt % STAGES;
        const uint32_t aST = sbase + s * STAGE_BYTES;
        const uint32_t bST = aST + BM * 128;

        #pragma unroll
        for (int kk = 0; kk < 64; kk += 16) {
            uint32_t af[MT][4], bf[NT][2];
            #pragma unroll
            for (int i = 0; i < MT; i++) {
                int row = wm0 + i * 16 + (lane & 15);
                int cb = (kk >> 3) + (lane >> 4);
                uint32_t ad = aST + row * 128 + (((cb ^ (row & 7))) << 4);
                asm volatile("ldmatrix.sync.aligned.m8n8.x4.shared.b16 {%0,%1,%2,%3}, [%4];"
                    : "=r"(af[i][0]), "=r"(af[i][1]), "=r"(af[i][2]), "=r"(af[i][3]) : "r"(ad));
            }
            #pragma unroll
            for (int j = 0; j < NT; j++) {
                int row = wn0 + j * 8 + (lane & 7);
                int cb = (kk >> 3) + ((lane >> 3) & 1);
                uint32_t bd = bST + row * 128 + (((cb ^ (row & 7))) << 4);
                asm volatile("ldmatrix.sync.aligned.m8n8.x2.shared.b16 {%0,%1}, [%2];"
                    : "=r"(bf[j][0]), "=r"(bf[j][1]) : "r"(bd));
            }
            #pragma unroll
            for (int j = 0; j < NT; j++)
                #pragma unroll
                for (int i = 0; i < MT; i++) mma16816(acc[i][j], af[i], bf[j]);
        }
        load_stage((kt + STAGES - 1) % STAGES, kt + STAGES - 1);
    }
    asm volatile("cp.async.wait_group 0;" ::: "memory");

    const int g = lane >> 2, tg = lane & 3;
    #pragma unroll
    for (int i = 0; i < MT; i++) {
        #pragma unroll
        for (int j = 0; j < NT; j++) {
            int cn = bn + wn0 + j * 8 + tg * 2;
            #pragma unroll
            for (int hh = 0; hh < 2; hh++) {
                int rm = bm + wm0 + i * 16 + g + hh * 8;
                float v0 = acc[i][j][hh * 2 + 0], v1 = acc[i][j][hh * 2 + 1];
                size_t o = (size_t)rm * ldc + cn;
                if (ATOMIC) {
                    atomicAdd(&C[o], v0);
                    atomicAdd(&C[o + 1], v1);
                } else {
                    if (bias) { v0 += bias[cn]; v1 += bias[cn + 1]; }
                    if (ACCUM) { v0 += C[o]; v1 += C[o + 1]; }
                    *reinterpret_cast<float2*>(&C[o]) = make_float2(v0, v1);
                }
            }
        }
    }
}

// ================= Non-pipelined HMMA GEMM (dt_proj, Keff=96) =================
template<int BM, int BN, int WARPS_M, int WARPS_N, bool ACCUM, int ACT, bool ATOMIC>
__global__ void __launch_bounds__(WARPS_M*WARPS_N*32)
mma_gemm(const __half* __restrict__ A6, const __half* __restrict__ B6,
         const float* __restrict__ bias, float* __restrict__ C, int ldc, int Keff)
{
    constexpr int NTHREADS = WARPS_M * WARPS_N * 32;
    constexpr int WM = BM / WARPS_M, WN = BN / WARPS_N;
    constexpr int MT = WM / 16, NT = WN / 8;
    constexpr int SK = 40;
    __shared__ __align__(16) __half As[BM * SK];
    __shared__ __align__(16) __half Bs[BN * SK];

    const int tid = threadIdx.x;
    const int lane = tid & 31, w = tid >> 5;
    const int wm0 = (w / WARPS_N) * WM;
    const int wn0 = (w % WARPS_N) * WN;
    const int bm = blockIdx.y * BM, bn = blockIdx.x * BN;
    const int g = lane >> 2, tg = lane & 3;

    int kbeg = 0, kend = Keff;
    if (ATOMIC) { int ks = Keff / gridDim.z; kbeg = blockIdx.z * ks; kend = kbeg + ks; }

    float acc[MT][NT][4];
    #pragma unroll
    for (int i = 0; i < MT; i++)
        #pragma unroll
        for (int j = 0; j < NT; j++)
            #pragma unroll
            for (int q = 0; q < 4; q++) acc[i][j][q] = 0.f;

    for (int k0 = kbeg; k0 < kend; k0 += 32) {
        #pragma unroll
        for (int rep = 0; rep < BM * 4 / NTHREADS; rep++) {
            int i = tid + rep * NTHREADS;
            int row = i >> 2, c = i & 3;
            *reinterpret_cast<uint4*>(&As[row * SK + c * 8]) =
                *reinterpret_cast<const uint4*>(&A6[(size_t)(bm + row) * Keff + k0 + c * 8]);
        }
        #pragma unroll
        for (int rep = 0; rep < BN * 4 / NTHREADS; rep++) {
            int i = tid + rep * NTHREADS;
            int row = i >> 2, c = i & 3;
            *reinterpret_cast<uint4*>(&Bs[row * SK + c * 8]) =
                *reinterpret_cast<const uint4*>(&B6[(size_t)(bn + row) * Keff + k0 + c * 8]);
        }
        __syncthreads();
        #pragma unroll
        for (int kk = 0; kk < 32; kk += 16) {
            uint32_t af[MT][4];
            #pragma unroll
            for (int i = 0; i < MT; i++) {
                const __half* base = &As[(wm0 + i * 16 + g) * SK + kk + tg * 2];
                af[i][0] = *reinterpret_cast<const uint32_t*>(base);
                af[i][1] = *reinterpret_cast<const uint32_t*>(base + 8 * SK);
                af[i][2] = *reinterpret_cast<const uint32_t*>(base + 8);
                af[i][3] = *reinterpret_cast<const uint32_t*>(base + 8 * SK + 8);
            }
            #pragma unroll
            for (int j = 0; j < NT; j++) {
                const __half* bb = &Bs[(wn0 + j * 8 + g) * SK + kk + tg * 2];
                uint32_t bfr[2] = { *reinterpret_cast<const uint32_t*>(bb),
                                    *reinterpret_cast<const uint32_t*>(bb + 8) };
                #pragma unroll
                for (int i = 0; i < MT; i++) mma16816(acc[i][j], af[i], bfr);
            }
        }
        __syncthreads();
    }

    #pragma unroll
    for (int i = 0; i < MT; i++) {
        #pragma unroll
        for (int j = 0; j < NT; j++) {
            int cn = bn + wn0 + j * 8 + tg * 2;
            #pragma unroll
            for (int hh = 0; hh < 2; hh++) {
                int rm = bm + wm0 + i * 16 + g + hh * 8;
                float v0 = acc[i][j][hh * 2 + 0], v1 = acc[i][j][hh * 2 + 1];
                size_t o = (size_t)rm * ldc + cn;
                if (ATOMIC) {
                    atomicAdd(&C[o], v0);
                    atomicAdd(&C[o + 1], v1);
                } else {
                    if (bias) { v0 += bias[cn]; v1 += bias[cn + 1]; }
                    if (ACT == 1) {
                        v0 = (v0 > 20.f) ? v0 : log1pf(__expf(v0));
                        v1 = (v1 > 20.f) ? v1 : log1pf(__expf(v1));
                    }
                    if (ACCUM) { v0 += C[o]; v1 += C[o + 1]; }
                    *reinterpret_cast<float2*>(&C[o]) = make_float2(v0, v1);
                }
            }
        }
    }
}

// ================= Mega weight-split prepass =================
#define NWD 22
struct SplitDescs {
    const float* W[NWD];
    __half*      dst[NWD];
    int K[NWD];
    int N[NWD];
    int tileBase[NWD];
};
// Each block: one 32x32 tile of one weight. W[K,N] fp32 -> dst[N,3K] halves [h,h,m].
__global__ void splitB_all(SplitDescs da)
{
    int t = blockIdx.x;
    int di = 0;
    #pragma unroll
    for (int i = 1; i < NWD; i++) if (t >= da.tileBase[i]) di = i;
    const float* W = da.W[di];
    __half* dst = da.dst[di];
    int K = da.K[di], N = da.N[di];
    int local = t - da.tileBase[di];
    int tilesN = N >> 5;
    int tk = local / tilesN, tn = local - tk * tilesN;
    int n0 = tn * 32, k0 = tk * 32;

    __shared__ float s[32][33];
    int tx = threadIdx.x, ty = threadIdx.y;   // (32,8)
    #pragma unroll
    for (int j = 0; j < 32; j += 8)
        s[ty + j][tx] = W[(size_t)(k0 + ty + j) * N + n0 + tx];
    __syncthreads();
    int Keff = 3 * K;
    #pragma unroll
    for (int j = 0; j < 32; j += 8) {
        int n = n0 + ty + j, k = k0 + tx;
        __half h, m; split2(s[tx][ty + j], h, m);
        __half* d = dst + (size_t)n * Keff + 3 * (size_t)k;
        d[0] = h; d[1] = h; d[2] = m;
    }
}

// ================= Activation split (row-major) =================
__global__ void splitA_kernel(const float* __restrict__ A, int lda, int k2shift, int total,
                              __half* __restrict__ A6)
{
    int idx = blockIdx.x * blockDim.x + threadIdx.x;
    if (idx >= total) return;
    int K2 = 1 << k2shift;
    int m = idx >> k2shift, kp = idx & (K2 - 1);
    float2 a = *reinterpret_cast<const float2*>(A + (size_t)m * lda + kp * 2);
    packA_pair(a.x, a.y, reinterpret_cast<uint32_t*>(A6 + (size_t)m * (6 * (size_t)K2) + kp * 6));
}

// ---------------- RMSNorm fused with A split (D=512) ----------------
__global__ void rmsnorm_split_kernel(const float* __restrict__ X,
                                     const float* __restrict__ w,
                                     __half* __restrict__ A6)
{
    int row = blockIdx.x;
    const float* x = X + (size_t)row * DM_;
    float s = 0.f;
    for (int j = threadIdx.x; j < DM_; j += 128) { float v = x[j]; s += v * v; }
    #pragma unroll
    for (int o = 16; o; o >>= 1) s += __shfl_xor_sync(0xffffffffu, s, o);
    __shared__ float ws[4];
    if ((threadIdx.x & 31) == 0) ws[threadIdx.x >> 5] = s;
    __syncthreads();
    float rs = rsqrtf((ws[0] + ws[1] + ws[2] + ws[3]) / (float)DM_ + 1e-5f);
    __half* dst = A6 + (size_t)row * (3 * DM_);
    for (int p = threadIdx.x; p < DM_ / 2; p += 128) {
        int k = p * 2;
        packA_pair(x[k] * rs * w[k], x[k + 1] * rs * w[k + 1],
                   reinterpret_cast<uint32_t*>(dst + p * 6));
    }
}

// ---------------- Depthwise conv (K=4) + SiLU, fused with A split ----------------
__global__ void conv_silu_split_kernel(const float* __restrict__ xz,
                                       const float* __restrict__ cw,
                                       const float* __restrict__ cb,
                                       float* __restrict__ xc,
                                       __half* __restrict__ A6)
{
    int idx = blockIdx.x * blockDim.x + threadIdx.x;
    if (idx >= B_ * LQ_ * (DI_ / 2)) return;
    int d2 = idx & 511;
    int l  = (idx >> 9) & 511;
    int b  = idx >> 18;
    int d  = d2 * 2;
    const float* base = xz + (size_t)b * LQ_ * 2 * DI_ + d;
    float s0 = cb[d], s1 = cb[d + 1];
    #pragma unroll
    for (int k = 0; k < 4; k++) {
        int ll = l - 3 + k;
        if (ll >= 0) {
            float2 v = *reinterpret_cast<const float2*>(base + (size_t)ll * (2 * DI_));
            s0 = fmaf(cw[d * 4 + k], v.x, s0);
            s1 = fmaf(cw[(d + 1) * 4 + k], v.y, s1);
        }
    }
    float y0 = s0 / (1.f + __expf(-s0));
    float y1 = s1 / (1.f + __expf(-s1));
    int row = b * LQ_ + l;
    *reinterpret_cast<float2*>(xc + (size_t)row * DI_ + d) = make_float2(y0, y1);
    packA_pair(y0, y1, reinterpret_cast<uint32_t*>(A6 + (size_t)row * (3 * DI_) + d2 * 6));
}

// ---------------- Selective scan: 4 threads per (b,d), fused with ys split ----------------
__global__ void scan_kernel(const float* __restrict__ delta,
                            const float* __restrict__ xc,
                            const float* __restrict__ dbl,
                            const float* __restrict__ xz,
                            const float* __restrict__ A_log,
                            const float* __restrict__ Dskip,
                            __half* __restrict__ A6)
{
    int t = blockIdx.x * blockDim.x + threadIdx.x;   // 32768 threads
    int ch = t >> 2, sub = t & 3;
    int d = ch & (DI_ - 1);
    int b = ch >> 10;
    int n0 = sub * 4;

    float A[4], h[4];
    #pragma unroll
    for (int j = 0; j < 4; j++) { A[j] = -__expf(A_log[d * DS_ + n0 + j]); h[j] = 0.f; }
    float Dv = Dskip[d];
    bool writer = ((t & 7) == 0);
    int d2 = d >> 1;

    for (int l = 0; l < LQ_; l++) {
        int row = b * LQ_ + l;
        float dt = delta[(size_t)row * DI_ + d];
        float u  = xc[(size_t)row * DI_ + d];
        float du = dt * u;
        float4 Bv = *reinterpret_cast<const float4*>(dbl + (size_t)row * 64 + DTR_ + n0);
        float4 Cv = *reinterpret_cast<const float4*>(dbl + (size_t)row * 64 + DTR_ + DS_ + n0);
        float y;
        {
            float dA0 = __expf(dt * A[0]); h[0] = fmaf(dA0, h[0], du * Bv.x);
            float dA1 = __expf(dt * A[1]); h[1] = fmaf(dA1, h[1], du * Bv.y);
            float dA2 = __expf(dt * A[2]); h[2] = fmaf(dA2, h[2], du * Bv.z);
            float dA3 = __expf(dt * A[3]); h[3] = fmaf(dA3, h[3], du * Bv.w);
            y = h[0] * Cv.x + h[1] * Cv.y + h[2] * Cv.z + h[3] * Cv.w;
        }
        y += __shfl_xor_sync(0xffffffffu, y, 1);
        y += __shfl_xor_sync(0xffffffffu, y, 2);
        float z = xz[(size_t)row * (2 * DI_) + DI_ + d];
        float sz = z / (1.f + __expf(-z));
        float yv = (y + u * Dv) * sz;
        float yo = __shfl_xor_sync(0xffffffffu, yv, 4);
        if (writer) {
            packA_pair(yv, yo,
                reinterpret_cast<uint32_t*>(A6 + (size_t)row * (3 * DI_) + d2 * 6));
        }
    }
}

// ---------------- Attention (fp32 SIMT) ----------------
__global__ void attn_kernel(const float* __restrict__ Q,
                            const float* __restrict__ Kb,
                            const float* __restrict__ Vb,
                            float* __restrict__ O)
{
    const int qt = blockIdx.x * 16;
    const int h  = blockIdx.y;
    const int b  = blockIdx.z;
    __shared__ float Qs[16][128];
    __shared__ float Ks[32][128];
    __shared__ float S[16][256];
    const int tid = threadIdx.x;

    #pragma unroll
    for (int j = 0; j < 8; j++) {
        int idx = tid + j * 256;
        int qi = idx >> 7, dd = idx & 127;
        Qs[qi][dd] = Q[((size_t)(b * LQ_ + qt + qi)) * DM_ + h * DH_ + dd];
    }
    const float scale = 0.08838834764831845f;
    for (int kc = 0; kc < 8; kc++) {
        #pragma unroll
        for (int j = 0; j < 16; j++) {
            int idx = tid + j * 256;
            int ki = idx >> 7, dd = idx & 127;
            Ks[ki][dd] = Kb[((size_t)(b * LK_ + kc * 32 + ki)) * DM_ + h * DH_ + dd];
        }
        __syncthreads();
        #pragma unroll
        for (int j = 0; j < 2; j++) {
            int p = tid + j * 256;
            int qi = p >> 5, ki = p & 31;
            float s = 0.f;
            #pragma unroll 4
            for (int dd = 0; dd < 128; dd++) s = fmaf(Qs[qi][dd], Ks[ki][dd], s);
            S[qi][kc * 32 + ki] = s * scale;
        }
        __syncthreads();
    }
    {
        int warp = tid >> 5, lane = tid & 31;
        for (int r = warp * 2; r < warp * 2 + 2; r++) {
            float m = -1e30f;
            #pragma unroll
            for (int j = lane; j < 256; j += 32) m = fmaxf(m, S[r][j]);
            #pragma unroll
            for (int o = 16; o; o >>= 1) m = fmaxf(m, __shfl_xor_sync(0xffffffffu, m, o));
            float sum = 0.f;
            #pragma unroll
            for (int j = lane; j < 256; j += 32) {
                float e = __expf(S[r][j] - m);
                S[r][j] = e; sum += e;
            }
            #pragma unroll
            for (int o = 16; o; o >>= 1) sum += __shfl_xor_sync(0xffffffffu, sum, o);
            float inv = 1.f / sum;
            #pragma unroll
            for (int j = lane; j < 256; j += 32) S[r][j] *= inv;
        }
    }
    __syncthreads();
    {
        int dd = tid & 127, qg = tid >> 7;
        float acc[8];
        #pragma unroll
        for (int r = 0; r < 8; r++) acc[r] = 0.f;
        for (int k = 0; k < 256; k++) {
            float v = Vb[((size_t)(b * LK_ + k)) * DM_ + h * DH_ + dd];
            #pragma unroll
            for (int r = 0; r < 8; r++) acc[r] = fmaf(S[qg * 8 + r][k], v, acc[r]);
        }
        #pragma unroll
        for (int r = 0; r < 8; r++) {
            int qi = qg * 8 + r;
            O[((size_t)(b * LQ_ + qt + qi)) * DM_ + h * DH_ + dd] = acc[r];
        }
    }
}

// ---------------- Small fp32 GEMM for the N=6 head ----------------
__global__ void head_gemm_kernel(const float* __restrict__ A,
                                 const float* __restrict__ W,
                                 const float* __restrict__ bias,
                                 float* __restrict__ C, int M, int N, int K)
{
    __shared__ __align__(16) float As[16][64];
    __shared__ float Ws[16][8];
    const int bm = blockIdx.y * 64;
    const int tid = threadIdx.x;
    const int tx = tid & 15, ty = tid >> 4;
    float acc[4] = {0.f, 0.f, 0.f, 0.f};
    for (int k0 = 0; k0 < K; k0 += 16) {
        #pragma unroll
        for (int j = 0; j < 4; j++) {
            int idx = tid + j * 256;
            int m = idx >> 4, k = idx & 15;
            As[k][m] = A[(size_t)(bm + m) * K + (k0 + k)];
        }
        if (tid < 16 * 8) {
            int k = tid >> 3, n = tid & 7;
            Ws[k][n] = (n < N) ? W[(size_t)(k0 + k) * N + n] : 0.f;
        }
        __syncthreads();
        if (tx < 8) {
            #pragma unroll
            for (int k = 0; k < 16; k++) {
                float wv = Ws[k][tx];
                #pragma unroll
                for (int r = 0; r < 4; r++) acc[r] = fmaf(As[k][ty * 4 + r], wv, acc[r]);
            }
        }
        __syncthreads();
    }
    if (tx < N) {
        #pragma unroll
        for (int r = 0; r < 4; r++)
            C[(size_t)(bm + ty * 4 + r) * N + tx] = acc[r] + bias[tx];
    }
}

// ---------------- Argmax ----------------
__global__ void argmax_kernel(const float* __restrict__ probs, float* __restrict__ preds)
{
    int i = blockIdx.x * blockDim.x + threadIdx.x;
    if (i >= ROWS_Q) return;
    const float* p = probs + (size_t)i * NOUT_;
    float best = p[0]; int bi = 0;
    #pragma unroll
    for (int j = 1; j < NOUT_; j++) if (p[j] > best) { best = p[j]; bi = j; }
    preds[i] = (float)bi;
}

// ---------------- Host launch ----------------
#define SMEM_PIPE_128 (3 * (128 + 128) * 128)   // 98304
#define SMEM_PIPE_64  (3 * (128 + 64) * 128)    // 73728

extern "C" void kernel_launch(void* const* d_in, const int* in_sizes, int n_in,
                              void* d_out, int out_size)
{
    const float* agent   = (const float*)d_in[0];
    const float* lane    = (const float*)d_in[1];
    const float* lane_W  = (const float*)d_in[2];
    const float* lane_b  = (const float*)d_in[3];
    const float* norm_w  = (const float*)d_in[4];
    const float* inpW    = (const float*)d_in[5];
    const float* convw   = (const float*)d_in[6];
    const float* convb   = (const float*)d_in[7];
    const float* xprW    = (const float*)d_in[8];
    const float* dtW     = (const float*)d_in[9];
    const float* dtb     = (const float*)d_in[10];
    const float* A_log   = (const float*)d_in[11];
    const float* Dskip   = (const float*)d_in[12];
    const float* outW    = (const float*)d_in[13];
    const float* fnw     = (const float*)d_in[14];
    const float* Wq      = (const float*)d_in[15];
    const float* Wk      = (const float*)d_in[16];
    const float* Wv      = (const float*)d_in[17];
    const float* Wo      = (const float*)d_in[18];
    const float* bq      = (const float*)d_in[19];
    const float* bk      = (const float*)d_in[20];
    const float* bv      = (const float*)d_in[21];
    const float* bo      = (const float*)d_in[22];
    const float* linW    = (const float*)d_in[23];
    const float* linb    = (const float*)d_in[24];
    const float* loutW   = (const float*)d_in[25];
    const float* loutb   = (const float*)d_in[26];

    float *px, *ph, *pxz, *pxc, *pdbl, *pdlt, *pq, *pk, *pv, *patt;
    __half *pA6, *pAag, *pB;
    cudaGetSymbolAddress((void**)&px,   g_x);
    cudaGetSymbolAddress((void**)&ph,   g_h);
    cudaGetSymbolAddress((void**)&pxz,  g_xz);
    cudaGetSymbolAddress((void**)&pxc,  g_xc);
    cudaGetSymbolAddress((void**)&pdbl, g_dbl);
    cudaGetSymbolAddress((void**)&pdlt, g_dlt);
    cudaGetSymbolAddress((void**)&pq,   g_q);
    cudaGetSymbolAddress((void**)&pk,   g_k);
    cudaGetSymbolAddress((void**)&pv,   g_v);
    cudaGetSymbolAddress((void**)&patt, g_att);
    cudaGetSymbolAddress((void**)&pA6,  g_A6);
    cudaGetSymbolAddress((void**)&pAag, g_Aag);
    cudaGetSymbolAddress((void**)&pB,   g_B6all);

    cudaFuncSetAttribute(mma_gemm_pipe<128,128,false,false>,
                         cudaFuncAttributeMaxDynamicSharedMemorySize, SMEM_PIPE_128);
    cudaFuncSetAttribute(mma_gemm_pipe<128,128,true,false>,
                         cudaFuncAttributeMaxDynamicSharedMemorySize, SMEM_PIPE_128);
    cudaFuncSetAttribute(mma_gemm_pipe<128,64,false,true>,
                         cudaFuncAttributeMaxDynamicSharedMemorySize, SMEM_PIPE_64);

    float* probs = (float*)d_out;

    // ---- build weight-split descriptor table ----
    SplitDescs da;
    __half* bLane;  __half* bIn[4]; __half* bXp[4]; __half* bDt[4]; __half* bOut[4];
    __half* bQ; __half* bK; __half* bV; __half* bO; __half* bLin;
    {
        int di = 0; size_t off = 0; int tiles = 0;
        auto add = [&](const float* W, int K, int N, __half** save) {
            da.W[di] = W; da.dst[di] = pB + off; da.K[di] = K; da.N[di] = N;
            da.tileBase[di] = tiles;
            *save = pB + off;
            off += (size_t)N * 3 * K;
            tiles += (K >> 5) * (N >> 5);
            di++;
        };
        add(lane_W, 128, DM_, &bLane);
        for (int i = 0; i < 4; i++) add(inpW + (size_t)i * DM_ * 2 * DI_, DM_, 2 * DI_, &bIn[i]);
        for (int i = 0; i < 4; i++) add(xprW + (size_t)i * DI_ * 64,      DI_, 64,      &bXp[i]);
        for (int i = 0; i < 4; i++) add(dtW  + (size_t)i * DTR_ * DI_,    DTR_, DI_,    &bDt[i]);
        for (int i = 0; i < 4; i++) add(outW + (size_t)i * DI_ * DM_,     DI_, DM_,     &bOut[i]);
        add(Wq,  DM_, DM_, &bQ);
        add(Wk,  DM_, DM_, &bK);
        add(Wv,  DM_, DM_, &bV);
        add(Wo,  DM_, DM_, &bO);
        add(linW, DM_, DM_, &bLin);
        // total tiles = 7872, total halves ~24.2M
        splitB_all<<<tiles, dim3(32, 8)>>>(da);
    }
    // agent activation split (constant input) up front
    splitA_kernel<<<(ROWS_K * 256 + 255) / 256, 256>>>(agent, DM_, 8, ROWS_K * 256, pAag);

    // ---- lane_in: x = lane @ lane_W + lane_b (Keff=384) ----
    splitA_kernel<<<(ROWS_Q * 64 + 255) / 256, 256>>>(lane, 128, 6, ROWS_Q * 64, pA6);
    mma_gemm_pipe<128,128,false,false><<<dim3(DM_/128, ROWS_Q/128), 512, SMEM_PIPE_128>>>(pA6, bLane, lane_b, px, DM_, 3*128);

    for (int i = 0; i < NBLK_; i++) {
        rmsnorm_split_kernel<<<ROWS_Q, 128>>>(px, norm_w + i * DM_, pA6);
        // in_proj: Keff=1536, N=2048
        mma_gemm_pipe<128,128,false,false><<<dim3(2*DI_/128, ROWS_Q/128), 512, SMEM_PIPE_128>>>(pA6, bIn[i], nullptr, pxz, 2*DI_, 3*DM_);
        conv_silu_split_kernel<<<(B_*LQ_*DI_/2 + 255) / 256, 256>>>(pxz,
            convw + (size_t)i * DI_ * 4, convb + (size_t)i * DI_, pxc, pA6);
        // x_proj: Keff=3072, N=64, split-K=4 atomic
        cudaMemsetAsync(pdbl, 0, (size_t)ROWS_Q * 64 * sizeof(float));
        mma_gemm_pipe<128,64,false,true><<<dim3(1, ROWS_Q/128, 4), 512, SMEM_PIPE_64>>>(pA6, bXp[i], nullptr, pdbl, 64, 3*DI_);
        // dt_proj (softplus): Keff=96, N=1024 (non-pipelined)
        splitA_kernel<<<(ROWS_Q * 16 + 255) / 256, 256>>>(pdbl, 64, 4, ROWS_Q * 16, pA6);
        mma_gemm<128,128,2,4,false,1,false><<<dim3(DI_/128, ROWS_Q/128), 256>>>(pA6, bDt[i], dtb + (size_t)i * DI_, pdlt, DI_, 3*DTR_);
        // scan -> A6 (out_proj A)
        scan_kernel<<<128, 256>>>(pdlt, pxc, pdbl, pxz,
            A_log + (size_t)i * DI_ * DS_, Dskip + (size_t)i * DI_, pA6);
        // out_proj (+= residual): Keff=3072, N=512
        mma_gemm_pipe<128,128,true,false><<<dim3(DM_/128, ROWS_Q/128), 512, SMEM_PIPE_128>>>(pA6, bOut[i], nullptr, px, DM_, 3*DI_);
    }

    rmsnorm_split_kernel<<<ROWS_Q, 128>>>(px, fnw, pA6);
    mma_gemm_pipe<128,128,false,false><<<dim3(DM_/128, ROWS_Q/128), 512, SMEM_PIPE_128>>>(pA6, bQ, bq, pq, DM_, 3*DM_);

    mma_gemm_pipe<128,128,false,false><<<dim3(DM_/128, ROWS_K/128), 512, SMEM_PIPE_128>>>(pAag, bK, bk, pk, DM_, 3*DM_);
    mma_gemm_pipe<128,128,false,false><<<dim3(DM_/128, ROWS_K/128), 512, SMEM_PIPE_128>>>(pAag, bV, bv, pv, DM_, 3*DM_);

    attn_kernel<<<dim3(LQ_/16, NHEAD_, B_), 256>>>(pq, pk, pv, patt);

    splitA_kernel<<<(ROWS_Q * 256 + 255) / 256, 256>>>(patt, DM_, 8, ROWS_Q * 256, pA6);
    mma_gemm_pipe<128,128,false,false><<<dim3(DM_/128, ROWS_Q/128), 512, SMEM_PIPE_128>>>(pA6, bO, bo, px, DM_, 3*DM_);

    splitA_kernel<<<(ROWS_Q * 256 + 255) / 256, 256>>>(px, DM_, 8, ROWS_Q * 256, pA6);
    mma_gemm_pipe<128,128,false,false><<<dim3(DM_/128, ROWS_Q/128), 512, SMEM_PIPE_128>>>(pA6, bLin, linb, ph, DM_, 3*DM_);

    head_gemm_kernel<<<dim3(1, ROWS_Q/64), 256>>>(ph, loutW, loutb, probs, ROWS_Q, NOUT_, DM_);
    if (out_size >= ROWS_Q * NOUT_ + ROWS_Q) {
        argmax_kernel<<<(ROWS_Q + 255) / 256, 256>>>(probs, probs + ROWS_Q * NOUT_);
    }
}

// round 12
// speedup vs baseline: 1.4708x; 1.4708x over previous
#include <cuda_runtime.h>
#include <cuda_fp16.h>
#include <math.h>
#include <stdint.h>

// ---------------- Problem dims ----------------
#define B_      8
#define LQ_     512
#define LK_     256
#define DM_     512
#define DI_     1024
#define DS_     16
#define DTR_    32
#define NBLK_   4
#define NHEAD_  4
#define DH_     128
#define NOUT_   6

#define ROWS_Q  (B_*LQ_)   // 4096
#define ROWS_K  (B_*LK_)   // 2048

// ---------------- Scratch (static device globals; no allocation) ----------------
__device__ float g_x   [ROWS_Q * DM_];
__device__ float g_h   [ROWS_Q * DM_];
__device__ float g_xz  [ROWS_Q * 2 * DI_];
__device__ float g_xc  [ROWS_Q * DI_];
__device__ float g_dbl [ROWS_Q * 64];
__device__ float g_dlt [ROWS_Q * DI_];
__device__ float g_q   [ROWS_Q * DM_];
__device__ float g_k   [ROWS_K * DM_];
__device__ float g_v   [ROWS_K * DM_];
__device__ float g_att [ROWS_Q * DM_];
__device__ __align__(16) __half g_A6   [ROWS_Q * 3 * 1024];   // activation splits
__device__ __align__(16) __half g_Aag  [ROWS_K * 3 * 512];    // agent split (constant input)
__device__ __align__(16) __half g_B6all[25600000];            // all weight splits (~48.4MB used)

// ---------------- fp16 split helpers ----------------
__device__ __forceinline__ uint32_t pack2h(__half a, __half b) {
    return (uint32_t)__half_as_ushort(a) | ((uint32_t)__half_as_ushort(b) << 16);
}
__device__ __forceinline__ void split2(float a, __half& h, __half& m) {
    h = __float2half(a);
    m = __float2half(a - __half2float(h));
}
// pack a pair of A-elements into 3 u32: halves [h0,m0,h0,h1,m1,h1]
__device__ __forceinline__ void packA_pair(float a0, float a1, uint32_t* dst) {
    __half h0, m0, h1, m1;
    split2(a0, h0, m0); split2(a1, h1, m1);
    dst[0] = pack2h(h0, m0);
    dst[1] = pack2h(h0, h1);
    dst[2] = pack2h(m1, h1);
}
__device__ __forceinline__ uint32_t smem_u32(const void* p) {
    uint32_t a;
    asm("{ .reg .u64 t; cvta.to.shared.u64 t, %1; cvt.u32.u64 %0, t; }" : "=r"(a) : "l"(p));
    return a;
}

// ---------------- mma.sync m16n8k16 f16->f32 ----------------
__device__ __forceinline__ void mma16816(float* c, const uint32_t* a, const uint32_t* b) {
    asm volatile("mma.sync.aligned.m16n8k16.row.col.f32.f16.f16.f32 "
        "{%0,%1,%2,%3}, {%4,%5,%6,%7}, {%8,%9}, {%0,%1,%2,%3};"
        : "+f"(c[0]), "+f"(c[1]), "+f"(c[2]), "+f"(c[3])
        : "r"(a[0]), "r"(a[1]), "r"(a[2]), "r"(a[3]), "r"(b[0]), "r"(b[1]));
}

// ================= Pipelined HMMA GEMM (256 threads, 8 warps 2x4) =================
// C[M,N] = A6[M,Keff] * B6[N,Keff]^T.  Keff % 64 == 0 (per split-K slice).
// BK = 64 halves (128B rows, XOR-swizzled). Warp tile = (BM/2) x (BN/4).
template<int BM, int BN, bool ACCUM, bool ATOMIC>
__global__ void __launch_bounds__(256)
mma_gemm_pipe(const __half* __restrict__ A6, const __half* __restrict__ B6,
              const float* __restrict__ bias, float* __restrict__ C, int ldc, int Keff)
{
    constexpr int STAGES = 3;
    constexpr int WM = BM / 2, WN = BN / 4;
    constexpr int MT = WM / 16, NT = WN / 8;
    constexpr int STAGE_BYTES = (BM + BN) * 128;
    extern __shared__ __align__(16) char smem[];
    const uint32_t sbase = smem_u32(smem);

    const int tid = threadIdx.x, lane = tid & 31, w = tid >> 5;
    const int wm0 = (w >> 2) * WM, wn0 = (w & 3) * WN;
    const int bm = blockIdx.y * BM, bn = blockIdx.x * BN;

    int ktiles = Keff >> 6;
    int kbeg = 0;
    if (ATOMIC) { int kt = ktiles / gridDim.z; kbeg = blockIdx.z * kt; ktiles = kt; }

    auto load_stage = [&](int s, int kt) {
        if (kt >= ktiles) {
            asm volatile("cp.async.commit_group;" ::: "memory");
            return;
        }
        const uint32_t aST = sbase + s * STAGE_BYTES;
        const uint32_t bST = aST + BM * 128;
        const size_t gk = ((size_t)(kbeg + kt)) << 6;
        #pragma unroll
        for (int r = 0; r < BM * 8 / 256; r++) {
            int idx = tid + r * 256;
            int row = idx >> 3, cc = idx & 7;
            uint32_t d = aST + row * 128 + ((cc ^ (row & 7)) << 4);
            const __half* g = A6 + (size_t)(bm + row) * Keff + gk + cc * 8;
            asm volatile("cp.async.cg.shared.global [%0], [%1], 16;" :: "r"(d), "l"(g));
        }
        #pragma unroll
        for (int r = 0; r < BN * 8 / 256; r++) {
            int idx = tid + r * 256;
            int row = idx >> 3, cc = idx & 7;
            uint32_t d = bST + row * 128 + ((cc ^ (row & 7)) << 4);
            const __half* g = B6 + (size_t)(bn + row) * Keff + gk + cc * 8;
            asm volatile("cp.async.cg.shared.global [%0], [%1], 16;" :: "r"(d), "l"(g));
        }
        asm volatile("cp.async.commit_group;" ::: "memory");
    };

    float acc[MT][NT][4];
    #pragma unroll
    for (int i = 0; i < MT; i++)
        #pragma unroll
        for (int j = 0; j < NT; j++)
            #pragma unroll
            for (int q = 0; q < 4; q++) acc[i][j][q] = 0.f;

    #pragma unroll
    for (int s = 0; s < STAGES - 1; s++) load_stage(s, s);

    for (int kt = 0; kt < ktiles; kt++) {
        asm volatile("cp.async.wait_group %0;" :: "n"(STAGES - 2) : "memory");
        __syncthreads();
        const int s = kt % STAGES;
        const uint32_t aST = sbase + s * STAGE_BYTES;
        const uint32_t bST = aST + BM * 128;

        #pragma unroll
        for (int kk = 0; kk < 64; kk += 16) {
            uint32_t af[MT][4], bf[NT][2];
            #pragma unroll
            for (int i = 0; i < MT; i++) {
                int row = wm0 + i * 16 + (lane & 15);
                int cb = (kk >> 3) + (lane >> 4);
                uint32_t ad = aST + row * 128 + (((cb ^ (row & 7))) << 4);
                asm volatile("ldmatrix.sync.aligned.m8n8.x4.shared.b16 {%0,%1,%2,%3}, [%4];"
                    : "=r"(af[i][0]), "=r"(af[i][1]), "=r"(af[i][2]), "=r"(af[i][3]) : "r"(ad));
            }
            #pragma unroll
            for (int j = 0; j < NT; j++) {
                int row = wn0 + j * 8 + (lane & 7);
                int cb = (kk >> 3) + ((lane >> 3) & 1);
                uint32_t bd = bST + row * 128 + (((cb ^ (row & 7))) << 4);
                asm volatile("ldmatrix.sync.aligned.m8n8.x2.shared.b16 {%0,%1}, [%2];"
                    : "=r"(bf[j][0]), "=r"(bf[j][1]) : "r"(bd));
            }
            #pragma unroll
            for (int j = 0; j < NT; j++)
                #pragma unroll
                for (int i = 0; i < MT; i++) mma16816(acc[i][j], af[i], bf[j]);
        }
        load_stage((kt + STAGES - 1) % STAGES, kt + STAGES - 1);
    }
    asm volatile("cp.async.wait_group 0;" ::: "memory");

    const int g = lane >> 2, tg = lane & 3;
    #pragma unroll
    for (int i = 0; i < MT; i++) {
        #pragma unroll
        for (int j = 0; j < NT; j++) {
            int cn = bn + wn0 + j * 8 + tg * 2;
            #pragma unroll
            for (int hh = 0; hh < 2; hh++) {
                int rm = bm + wm0 + i * 16 + g + hh * 8;
                float v0 = acc[i][j][hh * 2 + 0], v1 = acc[i][j][hh * 2 + 1];
                size_t o = (size_t)rm * ldc + cn;
                if (ATOMIC) {
                    atomicAdd(&C[o], v0);
                    atomicAdd(&C[o + 1], v1);
                } else {
                    if (bias) { v0 += bias[cn]; v1 += bias[cn + 1]; }
                    if (ACCUM) { v0 += C[o]; v1 += C[o + 1]; }
                    *reinterpret_cast<float2*>(&C[o]) = make_float2(v0, v1);
                }
            }
        }
    }
}

// ================= Non-pipelined HMMA GEMM (dt_proj, Keff=96) =================
template<int BM, int BN, int WARPS_M, int WARPS_N, bool ACCUM, int ACT, bool ATOMIC>
__global__ void __launch_bounds__(WARPS_M*WARPS_N*32)
mma_gemm(const __half* __restrict__ A6, const __half* __restrict__ B6,
         const float* __restrict__ bias, float* __restrict__ C, int ldc, int Keff)
{
    constexpr int NTHREADS = WARPS_M * WARPS_N * 32;
    constexpr int WM = BM / WARPS_M, WN = BN / WARPS_N;
    constexpr int MT = WM / 16, NT = WN / 8;
    constexpr int SK = 40;
    __shared__ __align__(16) __half As[BM * SK];
    __shared__ __align__(16) __half Bs[BN * SK];

    const int tid = threadIdx.x;
    const int lane = tid & 31, w = tid >> 5;
    const int wm0 = (w / WARPS_N) * WM;
    const int wn0 = (w % WARPS_N) * WN;
    const int bm = blockIdx.y * BM, bn = blockIdx.x * BN;
    const int g = lane >> 2, tg = lane & 3;

    int kbeg = 0, kend = Keff;
    if (ATOMIC) { int ks = Keff / gridDim.z; kbeg = blockIdx.z * ks; kend = kbeg + ks; }

    float acc[MT][NT][4];
    #pragma unroll
    for (int i = 0; i < MT; i++)
        #pragma unroll
        for (int j = 0; j < NT; j++)
            #pragma unroll
            for (int q = 0; q < 4; q++) acc[i][j][q] = 0.f;

    for (int k0 = kbeg; k0 < kend; k0 += 32) {
        #pragma unroll
        for (int rep = 0; rep < BM * 4 / NTHREADS; rep++) {
            int i = tid + rep * NTHREADS;
            int row = i >> 2, c = i & 3;
            *reinterpret_cast<uint4*>(&As[row * SK + c * 8]) =
                *reinterpret_cast<const uint4*>(&A6[(size_t)(bm + row) * Keff + k0 + c * 8]);
        }
        #pragma unroll
        for (int rep = 0; rep < BN * 4 / NTHREADS; rep++) {
            int i = tid + rep * NTHREADS;
            int row = i >> 2, c = i & 3;
            *reinterpret_cast<uint4*>(&Bs[row * SK + c * 8]) =
                *reinterpret_cast<const uint4*>(&B6[(size_t)(bn + row) * Keff + k0 + c * 8]);
        }
        __syncthreads();
        #pragma unroll
        for (int kk = 0; kk < 32; kk += 16) {
            uint32_t af[MT][4];
            #pragma unroll
            for (int i = 0; i < MT; i++) {
                const __half* base = &As[(wm0 + i * 16 + g) * SK + kk + tg * 2];
                af[i][0] = *reinterpret_cast<const uint32_t*>(base);
                af[i][1] = *reinterpret_cast<const uint32_t*>(base + 8 * SK);
                af[i][2] = *reinterpret_cast<const uint32_t*>(base + 8);
                af[i][3] = *reinterpret_cast<const uint32_t*>(base + 8 * SK + 8);
            }
            #pragma unroll
            for (int j = 0; j < NT; j++) {
                const __half* bb = &Bs[(wn0 + j * 8 + g) * SK + kk + tg * 2];
                uint32_t bfr[2] = { *reinterpret_cast<const uint32_t*>(bb),
                                    *reinterpret_cast<const uint32_t*>(bb + 8) };
                #pragma unroll
                for (int i = 0; i < MT; i++) mma16816(acc[i][j], af[i], bfr);
            }
        }
        __syncthreads();
    }

    #pragma unroll
    for (int i = 0; i < MT; i++) {
        #pragma unroll
        for (int j = 0; j < NT; j++) {
            int cn = bn + wn0 + j * 8 + tg * 2;
            #pragma unroll
            for (int hh = 0; hh < 2; hh++) {
                int rm = bm + wm0 + i * 16 + g + hh * 8;
                float v0 = acc[i][j][hh * 2 + 0], v1 = acc[i][j][hh * 2 + 1];
                size_t o = (size_t)rm * ldc + cn;
                if (ATOMIC) {
                    atomicAdd(&C[o], v0);
                    atomicAdd(&C[o + 1], v1);
                } else {
                    if (bias) { v0 += bias[cn]; v1 += bias[cn + 1]; }
                    if (ACT == 1) {
                        v0 = (v0 > 20.f) ? v0 : log1pf(__expf(v0));
                        v1 = (v1 > 20.f) ? v1 : log1pf(__expf(v1));
                    }
                    if (ACCUM) { v0 += C[o]; v1 += C[o + 1]; }
                    *reinterpret_cast<float2*>(&C[o]) = make_float2(v0, v1);
                }
            }
        }
    }
}

// ================= Mega weight-split prepass =================
#define NWD 22
struct SplitDescs {
    const float* W[NWD];
    __half*      dst[NWD];
    int K[NWD];
    int N[NWD];
    int tileBase[NWD];
};
// Each block: one 32x32 tile of one weight. W[K,N] fp32 -> dst[N,3K] halves [h,h,m].
__global__ void splitB_all(SplitDescs da)
{
    int t = blockIdx.x;
    int di = 0;
    #pragma unroll
    for (int i = 1; i < NWD; i++) if (t >= da.tileBase[i]) di = i;
    const float* W = da.W[di];
    __half* dst = da.dst[di];
    int K = da.K[di], N = da.N[di];
    int local = t - da.tileBase[di];
    int tilesN = N >> 5;
    int tk = local / tilesN, tn = local - tk * tilesN;
    int n0 = tn * 32, k0 = tk * 32;

    __shared__ float s[32][33];
    int tx = threadIdx.x, ty = threadIdx.y;   // (32,8)
    #pragma unroll
    for (int j = 0; j < 32; j += 8)
        s[ty + j][tx] = W[(size_t)(k0 + ty + j) * N + n0 + tx];
    __syncthreads();
    int Keff = 3 * K;
    #pragma unroll
    for (int j = 0; j < 32; j += 8) {
        int n = n0 + ty + j, k = k0 + tx;
        __half h, m; split2(s[tx][ty + j], h, m);
        __half* d = dst + (size_t)n * Keff + 3 * (size_t)k;
        d[0] = h; d[1] = h; d[2] = m;
    }
}

// ================= Activation split (row-major) =================
__global__ void splitA_kernel(const float* __restrict__ A, int lda, int k2shift, int total,
                              __half* __restrict__ A6)
{
    int idx = blockIdx.x * blockDim.x + threadIdx.x;
    if (idx >= total) return;
    int K2 = 1 << k2shift;
    int m = idx >> k2shift, kp = idx & (K2 - 1);
    float2 a = *reinterpret_cast<const float2*>(A + (size_t)m * lda + kp * 2);
    packA_pair(a.x, a.y, reinterpret_cast<uint32_t*>(A6 + (size_t)m * (6 * (size_t)K2) + kp * 6));
}

// ---------------- RMSNorm fused with A split (D=512) ----------------
__global__ void rmsnorm_split_kernel(const float* __restrict__ X,
                                     const float* __restrict__ w,
                                     __half* __restrict__ A6)
{
    int row = blockIdx.x;
    const float* x = X + (size_t)row * DM_;
    float s = 0.f;
    for (int j = threadIdx.x; j < DM_; j += 128) { float v = x[j]; s += v * v; }
    #pragma unroll
    for (int o = 16; o; o >>= 1) s += __shfl_xor_sync(0xffffffffu, s, o);
    __shared__ float ws[4];
    if ((threadIdx.x & 31) == 0) ws[threadIdx.x >> 5] = s;
    __syncthreads();
    float rs = rsqrtf((ws[0] + ws[1] + ws[2] + ws[3]) / (float)DM_ + 1e-5f);
    __half* dst = A6 + (size_t)row * (3 * DM_);
    for (int p = threadIdx.x; p < DM_ / 2; p += 128) {
        int k = p * 2;
        packA_pair(x[k] * rs * w[k], x[k + 1] * rs * w[k + 1],
                   reinterpret_cast<uint32_t*>(dst + p * 6));
    }
}

// ---------------- Depthwise conv (K=4) + SiLU, fused with A split ----------------
__global__ void conv_silu_split_kernel(const float* __restrict__ xz,
                                       const float* __restrict__ cw,
                                       const float* __restrict__ cb,
                                       float* __restrict__ xc,
                                       __half* __restrict__ A6)
{
    int idx = blockIdx.x * blockDim.x + threadIdx.x;
    if (idx >= B_ * LQ_ * (DI_ / 2)) return;
    int d2 = idx & 511;
    int l  = (idx >> 9) & 511;
    int b  = idx >> 18;
    int d  = d2 * 2;
    const float* base = xz + (size_t)b * LQ_ * 2 * DI_ + d;
    float s0 = cb[d], s1 = cb[d + 1];
    #pragma unroll
    for (int k = 0; k < 4; k++) {
        int ll = l - 3 + k;
        if (ll >= 0) {
            float2 v = *reinterpret_cast<const float2*>(base + (size_t)ll * (2 * DI_));
            s0 = fmaf(cw[d * 4 + k], v.x, s0);
            s1 = fmaf(cw[(d + 1) * 4 + k], v.y, s1);
        }
    }
    float y0 = s0 / (1.f + __expf(-s0));
    float y1 = s1 / (1.f + __expf(-s1));
    int row = b * LQ_ + l;
    *reinterpret_cast<float2*>(xc + (size_t)row * DI_ + d) = make_float2(y0, y1);
    packA_pair(y0, y1, reinterpret_cast<uint32_t*>(A6 + (size_t)row * (3 * DI_) + d2 * 6));
}

// ---------------- Selective scan: 4 threads per (b,d), fused with ys split ----------------
__global__ void scan_kernel(const float* __restrict__ delta,
                            const float* __restrict__ xc,
                            const float* __restrict__ dbl,
                            const float* __restrict__ xz,
                            const float* __restrict__ A_log,
                            const float* __restrict__ Dskip,
                            __half* __restrict__ A6)
{
    int t = blockIdx.x * blockDim.x + threadIdx.x;   // 32768 threads
    int ch = t >> 2, sub = t & 3;
    int d = ch & (DI_ - 1);
    int b = ch >> 10;
    int n0 = sub * 4;

    float A[4], h[4];
    #pragma unroll
    for (int j = 0; j < 4; j++) { A[j] = -__expf(A_log[d * DS_ + n0 + j]); h[j] = 0.f; }
    float Dv = Dskip[d];
    bool writer = ((t & 7) == 0);
    int d2 = d >> 1;

    for (int l = 0; l < LQ_; l++) {
        int row = b * LQ_ + l;
        float dt = delta[(size_t)row * DI_ + d];
        float u  = xc[(size_t)row * DI_ + d];
        float du = dt * u;
        float4 Bv = *reinterpret_cast<const float4*>(dbl + (size_t)row * 64 + DTR_ + n0);
        float4 Cv = *reinterpret_cast<const float4*>(dbl + (size_t)row * 64 + DTR_ + DS_ + n0);
        float y;
        {
            float dA0 = __expf(dt * A[0]); h[0] = fmaf(dA0, h[0], du * Bv.x);
            float dA1 = __expf(dt * A[1]); h[1] = fmaf(dA1, h[1], du * Bv.y);
            float dA2 = __expf(dt * A[2]); h[2] = fmaf(dA2, h[2], du * Bv.z);
            float dA3 = __expf(dt * A[3]); h[3] = fmaf(dA3, h[3], du * Bv.w);
            y = h[0] * Cv.x + h[1] * Cv.y + h[2] * Cv.z + h[3] * Cv.w;
        }
        y += __shfl_xor_sync(0xffffffffu, y, 1);
        y += __shfl_xor_sync(0xffffffffu, y, 2);
        float z = xz[(size_t)row * (2 * DI_) + DI_ + d];
        float sz = z / (1.f + __expf(-z));
        float yv = (y + u * Dv) * sz;
        float yo = __shfl_xor_sync(0xffffffffu, yv, 4);
        if (writer) {
            packA_pair(yv, yo,
                reinterpret_cast<uint32_t*>(A6 + (size_t)row * (3 * DI_) + d2 * 6));
        }
    }
}

// ---------------- Attention (fp32 SIMT) ----------------
__global__ void attn_kernel(const float* __restrict__ Q,
                            const float* __restrict__ Kb,
                            const float* __restrict__ Vb,
                            float* __restrict__ O)
{
    const int qt = blockIdx.x * 16;
    const int h  = blockIdx.y;
    const int b  = blockIdx.z;
    __shared__ float Qs[16][128];
    __shared__ float Ks[32][128];
    __shared__ float S[16][256];
    const int tid = threadIdx.x;

    #pragma unroll
    for (int j = 0; j < 8; j++) {
        int idx = tid + j * 256;
        int qi = idx >> 7, dd = idx & 127;
        Qs[qi][dd] = Q[((size_t)(b * LQ_ + qt + qi)) * DM_ + h * DH_ + dd];
    }
    const float scale = 0.08838834764831845f;
    for (int kc = 0; kc < 8; kc++) {
        #pragma unroll
        for (int j = 0; j < 16; j++) {
            int idx = tid + j * 256;
            int ki = idx >> 7, dd = idx & 127;
            Ks[ki][dd] = Kb[((size_t)(b * LK_ + kc * 32 + ki)) * DM_ + h * DH_ + dd];
        }
        __syncthreads();
        #pragma unroll
        for (int j = 0; j < 2; j++) {
            int p = tid + j * 256;
            int qi = p >> 5, ki = p & 31;
            float s = 0.f;
            #pragma unroll 4
            for (int dd = 0; dd < 128; dd++) s = fmaf(Qs[qi][dd], Ks[ki][dd], s);
            S[qi][kc * 32 + ki] = s * scale;
        }
        __syncthreads();
    }
    {
        int warp = tid >> 5, lane = tid & 31;
        for (int r = warp * 2; r < warp * 2 + 2; r++) {
            float m = -1e30f;
            #pragma unroll
            for (int j = lane; j < 256; j += 32) m = fmaxf(m, S[r][j]);
            #pragma unroll
            for (int o = 16; o; o >>= 1) m = fmaxf(m, __shfl_xor_sync(0xffffffffu, m, o));
            float sum = 0.f;
            #pragma unroll
            for (int j = lane; j < 256; j += 32) {
                float e = __expf(S[r][j] - m);
                S[r][j] = e; sum += e;
            }
            #pragma unroll
            for (int o = 16; o; o >>= 1) sum += __shfl_xor_sync(0xffffffffu, sum, o);
            float inv = 1.f / sum;
            #pragma unroll
            for (int j = lane; j < 256; j += 32) S[r][j] *= inv;
        }
    }
    __syncthreads();
    {
        int dd = tid & 127, qg = tid >> 7;
        float acc[8];
        #pragma unroll
        for (int r = 0; r < 8; r++) acc[r] = 0.f;
        for (int k = 0; k < 256; k++) {
            float v = Vb[((size_t)(b * LK_ + k)) * DM_ + h * DH_ + dd];
            #pragma unroll
            for (int r = 0; r < 8; r++) acc[r] = fmaf(S[qg * 8 + r][k], v, acc[r]);
        }
        #pragma unroll
        for (int r = 0; r < 8; r++) {
            int qi = qg * 8 + r;
            O[((size_t)(b * LQ_ + qt + qi)) * DM_ + h * DH_ + dd] = acc[r];
        }
    }
}

// ---------------- Small fp32 GEMM for the N=6 head ----------------
__global__ void head_gemm_kernel(const float* __restrict__ A,
                                 const float* __restrict__ W,
                                 const float* __restrict__ bias,
                                 float* __restrict__ C, int M, int N, int K)
{
    __shared__ __align__(16) float As[16][64];
    __shared__ float Ws[16][8];
    const int bm = blockIdx.y * 64;
    const int tid = threadIdx.x;
    const int tx = tid & 15, ty = tid >> 4;
    float acc[4] = {0.f, 0.f, 0.f, 0.f};
    for (int k0 = 0; k0 < K; k0 += 16) {
        #pragma unroll
        for (int j = 0; j < 4; j++) {
            int idx = tid + j * 256;
            int m = idx >> 4, k = idx & 15;
            As[k][m] = A[(size_t)(bm + m) * K + (k0 + k)];
        }
        if (tid < 16 * 8) {
            int k = tid >> 3, n = tid & 7;
            Ws[k][n] = (n < N) ? W[(size_t)(k0 + k) * N + n] : 0.f;
        }
        __syncthreads();
        if (tx < 8) {
            #pragma unroll
            for (int k = 0; k < 16; k++) {
                float wv = Ws[k][tx];
                #pragma unroll
                for (int r = 0; r < 4; r++) acc[r] = fmaf(As[k][ty * 4 + r], wv, acc[r]);
            }
        }
        __syncthreads();
    }
    if (tx < N) {
        #pragma unroll
        for (int r = 0; r < 4; r++)
            C[(size_t)(bm + ty * 4 + r) * N + tx] = acc[r] + bias[tx];
    }
}

// ---------------- Argmax ----------------
__global__ void argmax_kernel(const float* __restrict__ probs, float* __restrict__ preds)
{
    int i = blockIdx.x * blockDim.x + threadIdx.x;
    if (i >= ROWS_Q) return;
    const float* p = probs + (size_t)i * NOUT_;
    float best = p[0]; int bi = 0;
    #pragma unroll
    for (int j = 1; j < NOUT_; j++) if (p[j] > best) { best = p[j]; bi = j; }
    preds[i] = (float)bi;
}

// ---------------- Host launch ----------------
#define SMEM_PIPE_128 (3 * (128 + 128) * 128)   // 98304
#define SMEM_PIPE_64N (3 * (128 + 64) * 128)    // 73728 (128x64 atomic)
#define SMEM_PIPE_64M (3 * (64 + 128) * 128)    // 73728 (64x128)

extern "C" void kernel_launch(void* const* d_in, const int* in_sizes, int n_in,
                              void* d_out, int out_size)
{
    const float* agent   = (const float*)d_in[0];
    const float* lane    = (const float*)d_in[1];
    const float* lane_W  = (const float*)d_in[2];
    const float* lane_b  = (const float*)d_in[3];
    const float* norm_w  = (const float*)d_in[4];
    const float* inpW    = (const float*)d_in[5];
    const float* convw   = (const float*)d_in[6];
    const float* convb   = (const float*)d_in[7];
    const float* xprW    = (const float*)d_in[8];
    const float* dtW     = (const float*)d_in[9];
    const float* dtb     = (const float*)d_in[10];
    const float* A_log   = (const float*)d_in[11];
    const float* Dskip   = (const float*)d_in[12];
    const float* outW    = (const float*)d_in[13];
    const float* fnw     = (const float*)d_in[14];
    const float* Wq      = (const float*)d_in[15];
    const float* Wk      = (const float*)d_in[16];
    const float* Wv      = (const float*)d_in[17];
    const float* Wo      = (const float*)d_in[18];
    const float* bq      = (const float*)d_in[19];
    const float* bk      = (const float*)d_in[20];
    const float* bv      = (const float*)d_in[21];
    const float* bo      = (const float*)d_in[22];
    const float* linW    = (const float*)d_in[23];
    const float* linb    = (const float*)d_in[24];
    const float* loutW   = (const float*)d_in[25];
    const float* loutb   = (const float*)d_in[26];

    float *px, *ph, *pxz, *pxc, *pdbl, *pdlt, *pq, *pk, *pv, *patt;
    __half *pA6, *pAag, *pB;
    cudaGetSymbolAddress((void**)&px,   g_x);
    cudaGetSymbolAddress((void**)&ph,   g_h);
    cudaGetSymbolAddress((void**)&pxz,  g_xz);
    cudaGetSymbolAddress((void**)&pxc,  g_xc);
    cudaGetSymbolAddress((void**)&pdbl, g_dbl);
    cudaGetSymbolAddress((void**)&pdlt, g_dlt);
    cudaGetSymbolAddress((void**)&pq,   g_q);
    cudaGetSymbolAddress((void**)&pk,   g_k);
    cudaGetSymbolAddress((void**)&pv,   g_v);
    cudaGetSymbolAddress((void**)&patt, g_att);
    cudaGetSymbolAddress((void**)&pA6,  g_A6);
    cudaGetSymbolAddress((void**)&pAag, g_Aag);
    cudaGetSymbolAddress((void**)&pB,   g_B6all);

    cudaFuncSetAttribute(mma_gemm_pipe<128,128,false,false>,
                         cudaFuncAttributeMaxDynamicSharedMemorySize, SMEM_PIPE_128);
    cudaFuncSetAttribute(mma_gemm_pipe<128,64,false,true>,
                         cudaFuncAttributeMaxDynamicSharedMemorySize, SMEM_PIPE_64N);
    cudaFuncSetAttribute(mma_gemm_pipe<64,128,false,false>,
                         cudaFuncAttributeMaxDynamicSharedMemorySize, SMEM_PIPE_64M);
    cudaFuncSetAttribute(mma_gemm_pipe<64,128,true,false>,
                         cudaFuncAttributeMaxDynamicSharedMemorySize, SMEM_PIPE_64M);

    float* probs = (float*)d_out;

    // ---- build weight-split descriptor table ----
    SplitDescs da;
    __half* bLane;  __half* bIn[4]; __half* bXp[4]; __half* bDt[4]; __half* bOut[4];
    __half* bQ; __half* bK; __half* bV; __half* bO; __half* bLin;
    {
        int di = 0; size_t off = 0; int tiles = 0;
        auto add = [&](const float* W, int K, int N, __half** save) {
            da.W[di] = W; da.dst[di] = pB + off; da.K[di] = K; da.N[di] = N;
            da.tileBase[di] = tiles;
            *save = pB + off;
            off += (size_t)N * 3 * K;
            tiles += (K >> 5) * (N >> 5);
            di++;
        };
        add(lane_W, 128, DM_, &bLane);
        for (int i = 0; i < 4; i++) add(inpW + (size_t)i * DM_ * 2 * DI_, DM_, 2 * DI_, &bIn[i]);
        for (int i = 0; i < 4; i++) add(xprW + (size_t)i * DI_ * 64,      DI_, 64,      &bXp[i]);
        for (int i = 0; i < 4; i++) add(dtW  + (size_t)i * DTR_ * DI_,    DTR_, DI_,    &bDt[i]);
        for (int i = 0; i < 4; i++) add(outW + (size_t)i * DI_ * DM_,     DI_, DM_,     &bOut[i]);
        add(Wq,  DM_, DM_, &bQ);
        add(Wk,  DM_, DM_, &bK);
        add(Wv,  DM_, DM_, &bV);
        add(Wo,  DM_, DM_, &bO);
        add(linW, DM_, DM_, &bLin);
        // total tiles = 7872, total halves ~24.2M
        splitB_all<<<tiles, dim3(32, 8)>>>(da);
    }
    // agent activation split (constant input) up front
    splitA_kernel<<<(ROWS_K * 256 + 255) / 256, 256>>>(agent, DM_, 8, ROWS_K * 256, pAag);

    // ---- lane_in: x = lane @ lane_W + lane_b (Keff=384), grid 256 ----
    splitA_kernel<<<(ROWS_Q * 64 + 255) / 256, 256>>>(lane, 128, 6, ROWS_Q * 64, pA6);
    mma_gemm_pipe<64,128,false,false><<<dim3(DM_/128, ROWS_Q/64), 256, SMEM_PIPE_64M>>>(pA6, bLane, lane_b, px, DM_, 3*128);

    for (int i = 0; i < NBLK_; i++) {
        rmsnorm_split_kernel<<<ROWS_Q, 128>>>(px, norm_w + i * DM_, pA6);
        // in_proj: Keff=1536, N=2048, grid 512 (BM=128)
        mma_gemm_pipe<128,128,false,false><<<dim3(2*DI_/128, ROWS_Q/128), 256, SMEM_PIPE_128>>>(pA6, bIn[i], nullptr, pxz, 2*DI_, 3*DM_);
        conv_silu_split_kernel<<<(B_*LQ_*DI_/2 + 255) / 256, 256>>>(pxz,
            convw + (size_t)i * DI_ * 4, convb + (size_t)i * DI_, pxc, pA6);
        // x_proj: Keff=3072, N=64, split-K=4 atomic, grid 128
        cudaMemsetAsync(pdbl, 0, (size_t)ROWS_Q * 64 * sizeof(float));
        mma_gemm_pipe<128,64,false,true><<<dim3(1, ROWS_Q/128, 4), 256, SMEM_PIPE_64N>>>(pA6, bXp[i], nullptr, pdbl, 64, 3*DI_);
        // dt_proj (softplus): Keff=96, N=1024 (non-pipelined)
        splitA_kernel<<<(ROWS_Q * 16 + 255) / 256, 256>>>(pdbl, 64, 4, ROWS_Q * 16, pA6);
        mma_gemm<128,128,2,4,false,1,false><<<dim3(DI_/128, ROWS_Q/128), 256>>>(pA6, bDt[i], dtb + (size_t)i * DI_, pdlt, DI_, 3*DTR_);
        // scan -> A6 (out_proj A)
        scan_kernel<<<128, 256>>>(pdlt, pxc, pdbl, pxz,
            A_log + (size_t)i * DI_ * DS_, Dskip + (size_t)i * DI_, pA6);
        // out_proj (+= residual): Keff=3072, N=512, grid 256 (BM=64)
        mma_gemm_pipe<64,128,true,false><<<dim3(DM_/128, ROWS_Q/64), 256, SMEM_PIPE_64M>>>(pA6, bOut[i], nullptr, px, DM_, 3*DI_);
    }

    rmsnorm_split_kernel<<<ROWS_Q, 128>>>(px, fnw, pA6);
    mma_gemm_pipe<64,128,false,false><<<dim3(DM_/128, ROWS_Q/64), 256, SMEM_PIPE_64M>>>(pA6, bQ, bq, pq, DM_, 3*DM_);

    mma_gemm_pipe<64,128,false,false><<<dim3(DM_/128, ROWS_K/64), 256, SMEM_PIPE_64M>>>(pAag, bK, bk, pk, DM_, 3*DM_);
    mma_gemm_pipe<64,128,false,false><<<dim3(DM_/128, ROWS_K/64), 256, SMEM_PIPE_64M>>>(pAag, bV, bv, pv, DM_, 3*DM_);

    attn_kernel<<<dim3(LQ_/16, NHEAD_, B_), 256>>>(pq, pk, pv, patt);

    splitA_kernel<<<(ROWS_Q * 256 + 255) / 256, 256>>>(patt, DM_, 8, ROWS_Q * 256, pA6);
    mma_gemm_pipe<64,128,false,false><<<dim3(DM_/128, ROWS_Q/64), 256, SMEM_PIPE_64M>>>(pA6, bO, bo, px, DM_, 3*DM_);

    splitA_kernel<<<(ROWS_Q * 256 + 255) / 256, 256>>>(px, DM_, 8, ROWS_Q * 256, pA6);
    mma_gemm_pipe<64,128,false,false><<<dim3(DM_/128, ROWS_Q/64), 256, SMEM_PIPE_64M>>>(pA6, bLin, linb, ph, DM_, 3*DM_);

    head_gemm_kernel<<<dim3(1, ROWS_Q/64), 256>>>(ph, loutW, loutb, probs, ROWS_Q, NOUT_, DM_);
    if (out_size >= ROWS_Q * NOUT_ + ROWS_Q) {
        argmax_kernel<<<(ROWS_Q + 255) / 256, 256>>>(probs, probs + ROWS_Q * NOUT_);
    }
}

// round 13
// speedup vs baseline: 1.4721x; 1.0009x over previous
#include <cuda_runtime.h>
#include <cuda_fp16.h>
#include <math.h>
#include <stdint.h>

// ---------------- Problem dims ----------------
#define B_      8
#define LQ_     512
#define LK_     256
#define DM_     512
#define DI_     1024
#define DS_     16
#define DTR_    32
#define NBLK_   4
#define NHEAD_  4
#define DH_     128
#define NOUT_   6

#define ROWS_Q  (B_*LQ_)   // 4096
#define ROWS_K  (B_*LK_)   // 2048

// ---------------- Scratch (static device globals; no allocation) ----------------
__device__ float g_x   [ROWS_Q * DM_];
__device__ float g_h   [ROWS_Q * DM_];
__device__ float g_xz  [ROWS_Q * 2 * DI_];
__device__ float g_xc  [ROWS_Q * DI_];
__device__ float g_dbl [ROWS_Q * 64];
__device__ float g_dlt [ROWS_Q * DI_];
__device__ float g_q   [ROWS_Q * DM_];
__device__ float g_k   [ROWS_K * DM_];
__device__ float g_v   [ROWS_K * DM_];
__device__ float g_att [ROWS_Q * DM_];
__device__ __align__(16) __half g_A6   [ROWS_Q * 3 * 1024];   // activation splits
__device__ __align__(16) __half g_Aag  [ROWS_K * 3 * 512];    // agent split (constant input)
__device__ __align__(16) __half g_B6all[25600000];            // all weight splits (~48.4MB used)

// ---------------- fp16 split helpers ----------------
__device__ __forceinline__ uint32_t pack2h(__half a, __half b) {
    return (uint32_t)__half_as_ushort(a) | ((uint32_t)__half_as_ushort(b) << 16);
}
__device__ __forceinline__ void split2(float a, __half& h, __half& m) {
    h = __float2half(a);
    m = __float2half(a - __half2float(h));
}
// pack a pair of A-elements into 3 u32: halves [h0,m0,h0,h1,m1,h1]
__device__ __forceinline__ void packA_pair(float a0, float a1, uint32_t* dst) {
    __half h0, m0, h1, m1;
    split2(a0, h0, m0); split2(a1, h1, m1);
    dst[0] = pack2h(h0, m0);
    dst[1] = pack2h(h0, h1);
    dst[2] = pack2h(m1, h1);
}
__device__ __forceinline__ uint32_t smem_u32(const void* p) {
    uint32_t a;
    asm("{ .reg .u64 t; cvta.to.shared.u64 t, %1; cvt.u32.u64 %0, t; }" : "=r"(a) : "l"(p));
    return a;
}

// ---------------- mma.sync m16n8k16 f16->f32 ----------------
__device__ __forceinline__ void mma16816(float* c, const uint32_t* a, const uint32_t* b) {
    asm volatile("mma.sync.aligned.m16n8k16.row.col.f32.f16.f16.f32 "
        "{%0,%1,%2,%3}, {%4,%5,%6,%7}, {%8,%9}, {%0,%1,%2,%3};"
        : "+f"(c[0]), "+f"(c[1]), "+f"(c[2]), "+f"(c[3])
        : "r"(a[0]), "r"(a[1]), "r"(a[2]), "r"(a[3]), "r"(b[0]), "r"(b[1]));
}

// ================= Pipelined HMMA GEMM (256 threads, 8 warps 2x4) =================
// C[M,N] = A6[M,Keff] * B6[N,Keff]^T.  Keff % 64 == 0 (per split-K slice).
// BK = 64 halves (128B rows, XOR-swizzled). Warp tile = (BM/2) x (BN/4).
// Fragment double-buffering: ldmatrix for group g+1 overlaps HMMA of group g.
template<int BM, int BN, bool ACCUM, bool ATOMIC>
__global__ void __launch_bounds__(256)
mma_gemm_pipe(const __half* __restrict__ A6, const __half* __restrict__ B6,
              const float* __restrict__ bias, float* __restrict__ C, int ldc, int Keff)
{
    constexpr int STAGES = 3;
    constexpr int WM = BM / 2, WN = BN / 4;
    constexpr int MT = WM / 16, NT = WN / 8;
    constexpr int STAGE_BYTES = (BM + BN) * 128;
    extern __shared__ __align__(16) char smem[];
    const uint32_t sbase = smem_u32(smem);

    const int tid = threadIdx.x, lane = tid & 31, w = tid >> 5;
    const int wm0 = (w >> 2) * WM, wn0 = (w & 3) * WN;
    const int bm = blockIdx.y * BM, bn = blockIdx.x * BN;

    int ktiles = Keff >> 6;
    int kbeg = 0;
    if (ATOMIC) { int kt = ktiles / gridDim.z; kbeg = blockIdx.z * kt; ktiles = kt; }

    auto load_stage = [&](int s, int kt) {
        if (kt >= ktiles) {
            asm volatile("cp.async.commit_group;" ::: "memory");
            return;
        }
        const uint32_t aST = sbase + s * STAGE_BYTES;
        const uint32_t bST = aST + BM * 128;
        const size_t gk = ((size_t)(kbeg + kt)) << 6;
        #pragma unroll
        for (int r = 0; r < BM * 8 / 256; r++) {
            int idx = tid + r * 256;
            int row = idx >> 3, cc = idx & 7;
            uint32_t d = aST + row * 128 + ((cc ^ (row & 7)) << 4);
            const __half* g = A6 + (size_t)(bm + row) * Keff + gk + cc * 8;
            asm volatile("cp.async.cg.shared.global [%0], [%1], 16;" :: "r"(d), "l"(g));
        }
        #pragma unroll
        for (int r = 0; r < BN * 8 / 256; r++) {
            int idx = tid + r * 256;
            int row = idx >> 3, cc = idx & 7;
            uint32_t d = bST + row * 128 + ((cc ^ (row & 7)) << 4);
            const __half* g = B6 + (size_t)(bn + row) * Keff + gk + cc * 8;
            asm volatile("cp.async.cg.shared.global [%0], [%1], 16;" :: "r"(d), "l"(g));
        }
        asm volatile("cp.async.commit_group;" ::: "memory");
    };

    float acc[MT][NT][4];
    #pragma unroll
    for (int i = 0; i < MT; i++)
        #pragma unroll
        for (int j = 0; j < NT; j++)
            #pragma unroll
            for (int q = 0; q < 4; q++) acc[i][j][q] = 0.f;

    #pragma unroll
    for (int s = 0; s < STAGES - 1; s++) load_stage(s, s);

    uint32_t af[2][MT][4], bf[2][NT][2];

    for (int kt = 0; kt < ktiles; kt++) {
        asm volatile("cp.async.wait_group %0;" :: "n"(STAGES - 2) : "memory");
        __syncthreads();
        // slot (kt+2)%3 was freed when all threads finished kt-1's compute
        load_stage((kt + 2) % STAGES, kt + 2);

        const int s = kt % STAGES;
        const uint32_t aST = sbase + s * STAGE_BYTES;
        const uint32_t bST = aST + BM * 128;

        // --- fragment loader for k-group g (kk = g*16) into buffer buf ---
        auto load_frags = [&](int buf, int g) {
            const int kk = g * 16;
            #pragma unroll
            for (int i = 0; i < MT; i++) {
                int row = wm0 + i * 16 + (lane & 15);
                int cb = (kk >> 3) + (lane >> 4);
                uint32_t ad = aST + row * 128 + (((cb ^ (row & 7))) << 4);
                asm volatile("ldmatrix.sync.aligned.m8n8.x4.shared.b16 {%0,%1,%2,%3}, [%4];"
                    : "=r"(af[buf][i][0]), "=r"(af[buf][i][1]),
                      "=r"(af[buf][i][2]), "=r"(af[buf][i][3]) : "r"(ad));
            }
            #pragma unroll
            for (int j = 0; j < NT; j++) {
                int row = wn0 + j * 8 + (lane & 7);
                int cb = (kk >> 3) + ((lane >> 3) & 1);
                uint32_t bd = bST + row * 128 + (((cb ^ (row & 7))) << 4);
                asm volatile("ldmatrix.sync.aligned.m8n8.x2.shared.b16 {%0,%1}, [%2];"
                    : "=r"(bf[buf][j][0]), "=r"(bf[buf][j][1]) : "r"(bd));
            }
        };

        load_frags(0, 0);
        #pragma unroll
        for (int g = 0; g < 4; g++) {
            if (g < 3) load_frags((g + 1) & 1, g + 1);   // prefetch next group
            const int buf = g & 1;
            #pragma unroll
            for (int j = 0; j < NT; j++)
                #pragma unroll
                for (int i = 0; i < MT; i++) mma16816(acc[i][j], af[buf][i], bf[buf][j]);
        }
    }
    asm volatile("cp.async.wait_group 0;" ::: "memory");

    const int g = lane >> 2, tg = lane & 3;
    #pragma unroll
    for (int i = 0; i < MT; i++) {
        #pragma unroll
        for (int j = 0; j < NT; j++) {
            int cn = bn + wn0 + j * 8 + tg * 2;
            #pragma unroll
            for (int hh = 0; hh < 2; hh++) {
                int rm = bm + wm0 + i * 16 + g + hh * 8;
                float v0 = acc[i][j][hh * 2 + 0], v1 = acc[i][j][hh * 2 + 1];
                size_t o = (size_t)rm * ldc + cn;
                if (ATOMIC) {
                    atomicAdd(&C[o], v0);
                    atomicAdd(&C[o + 1], v1);
                } else {
                    if (bias) { v0 += bias[cn]; v1 += bias[cn + 1]; }
                    if (ACCUM) { v0 += C[o]; v1 += C[o + 1]; }
                    *reinterpret_cast<float2*>(&C[o]) = make_float2(v0, v1);
                }
            }
        }
    }
}

// ================= Non-pipelined HMMA GEMM (dt_proj, Keff=96) =================
template<int BM, int BN, int WARPS_M, int WARPS_N, bool ACCUM, int ACT, bool ATOMIC>
__global__ void __launch_bounds__(WARPS_M*WARPS_N*32)
mma_gemm(const __half* __restrict__ A6, const __half* __restrict__ B6,
         const float* __restrict__ bias, float* __restrict__ C, int ldc, int Keff)
{
    constexpr int NTHREADS = WARPS_M * WARPS_N * 32;
    constexpr int WM = BM / WARPS_M, WN = BN / WARPS_N;
    constexpr int MT = WM / 16, NT = WN / 8;
    constexpr int SK = 40;
    __shared__ __align__(16) __half As[BM * SK];
    __shared__ __align__(16) __half Bs[BN * SK];

    const int tid = threadIdx.x;
    const int lane = tid & 31, w = tid >> 5;
    const int wm0 = (w / WARPS_N) * WM;
    const int wn0 = (w % WARPS_N) * WN;
    const int bm = blockIdx.y * BM, bn = blockIdx.x * BN;
    const int g = lane >> 2, tg = lane & 3;

    int kbeg = 0, kend = Keff;
    if (ATOMIC) { int ks = Keff / gridDim.z; kbeg = blockIdx.z * ks; kend = kbeg + ks; }

    float acc[MT][NT][4];
    #pragma unroll
    for (int i = 0; i < MT; i++)
        #pragma unroll
        for (int j = 0; j < NT; j++)
            #pragma unroll
            for (int q = 0; q < 4; q++) acc[i][j][q] = 0.f;

    for (int k0 = kbeg; k0 < kend; k0 += 32) {
        #pragma unroll
        for (int rep = 0; rep < BM * 4 / NTHREADS; rep++) {
            int i = tid + rep * NTHREADS;
            int row = i >> 2, c = i & 3;
            *reinterpret_cast<uint4*>(&As[row * SK + c * 8]) =
                *reinterpret_cast<const uint4*>(&A6[(size_t)(bm + row) * Keff + k0 + c * 8]);
        }
        #pragma unroll
        for (int rep = 0; rep < BN * 4 / NTHREADS; rep++) {
            int i = tid + rep * NTHREADS;
            int row = i >> 2, c = i & 3;
            *reinterpret_cast<uint4*>(&Bs[row * SK + c * 8]) =
                *reinterpret_cast<const uint4*>(&B6[(size_t)(bn + row) * Keff + k0 + c * 8]);
        }
        __syncthreads();
        #pragma unroll
        for (int kk = 0; kk < 32; kk += 16) {
            uint32_t af[MT][4];
            #pragma unroll
            for (int i = 0; i < MT; i++) {
                const __half* base = &As[(wm0 + i * 16 + g) * SK + kk + tg * 2];
                af[i][0] = *reinterpret_cast<const uint32_t*>(base);
                af[i][1] = *reinterpret_cast<const uint32_t*>(base + 8 * SK);
                af[i][2] = *reinterpret_cast<const uint32_t*>(base + 8);
                af[i][3] = *reinterpret_cast<const uint32_t*>(base + 8 * SK + 8);
            }
            #pragma unroll
            for (int j = 0; j < NT; j++) {
                const __half* bb = &Bs[(wn0 + j * 8 + g) * SK + kk + tg * 2];
                uint32_t bfr[2] = { *reinterpret_cast<const uint32_t*>(bb),
                                    *reinterpret_cast<const uint32_t*>(bb + 8) };
                #pragma unroll
                for (int i = 0; i < MT; i++) mma16816(acc[i][j], af[i], bfr);
            }
        }
        __syncthreads();
    }

    #pragma unroll
    for (int i = 0; i < MT; i++) {
        #pragma unroll
        for (int j = 0; j < NT; j++) {
            int cn = bn + wn0 + j * 8 + tg * 2;
            #pragma unroll
            for (int hh = 0; hh < 2; hh++) {
                int rm = bm + wm0 + i * 16 + g + hh * 8;
                float v0 = acc[i][j][hh * 2 + 0], v1 = acc[i][j][hh * 2 + 1];
                size_t o = (size_t)rm * ldc + cn;
                if (ATOMIC) {
                    atomicAdd(&C[o], v0);
                    atomicAdd(&C[o + 1], v1);
                } else {
                    if (bias) { v0 += bias[cn]; v1 += bias[cn + 1]; }
                    if (ACT == 1) {
                        v0 = (v0 > 20.f) ? v0 : log1pf(__expf(v0));
                        v1 = (v1 > 20.f) ? v1 : log1pf(__expf(v1));
                    }
                    if (ACCUM) { v0 += C[o]; v1 += C[o + 1]; }
                    *reinterpret_cast<float2*>(&C[o]) = make_float2(v0, v1);
                }
            }
        }
    }
}

// ================= Mega weight-split prepass =================
#define NWD 22
struct SplitDescs {
    const float* W[NWD];
    __half*      dst[NWD];
    int K[NWD];
    int N[NWD];
    int tileBase[NWD];
};
// Each block: one 32x32 tile of one weight. W[K,N] fp32 -> dst[N,3K] halves [h,h,m].
__global__ void splitB_all(SplitDescs da)
{
    int t = blockIdx.x;
    int di = 0;
    #pragma unroll
    for (int i = 1; i < NWD; i++) if (t >= da.tileBase[i]) di = i;
    const float* W = da.W[di];
    __half* dst = da.dst[di];
    int K = da.K[di], N = da.N[di];
    int local = t - da.tileBase[di];
    int tilesN = N >> 5;
    int tk = local / tilesN, tn = local - tk * tilesN;
    int n0 = tn * 32, k0 = tk * 32;

    __shared__ float s[32][33];
    int tx = threadIdx.x, ty = threadIdx.y;   // (32,8)
    #pragma unroll
    for (int j = 0; j < 32; j += 8)
        s[ty + j][tx] = W[(size_t)(k0 + ty + j) * N + n0 + tx];
    __syncthreads();
    int Keff = 3 * K;
    #pragma unroll
    for (int j = 0; j < 32; j += 8) {
        int n = n0 + ty + j, k = k0 + tx;
        __half h, m; split2(s[tx][ty + j], h, m);
        __half* d = dst + (size_t)n * Keff + 3 * (size_t)k;
        d[0] = h; d[1] = h; d[2] = m;
    }
}

// ================= Activation split (row-major) =================
__global__ void splitA_kernel(const float* __restrict__ A, int lda, int k2shift, int total,
                              __half* __restrict__ A6)
{
    int idx = blockIdx.x * blockDim.x + threadIdx.x;
    if (idx >= total) return;
    int K2 = 1 << k2shift;
    int m = idx >> k2shift, kp = idx & (K2 - 1);
    float2 a = *reinterpret_cast<const float2*>(A + (size_t)m * lda + kp * 2);
    packA_pair(a.x, a.y, reinterpret_cast<uint32_t*>(A6 + (size_t)m * (6 * (size_t)K2) + kp * 6));
}

// ---------------- RMSNorm fused with A split (D=512) ----------------
__global__ void rmsnorm_split_kernel(const float* __restrict__ X,
                                     const float* __restrict__ w,
                                     __half* __restrict__ A6)
{
    int row = blockIdx.x;
    const float* x = X + (size_t)row * DM_;
    float s = 0.f;
    for (int j = threadIdx.x; j < DM_; j += 128) { float v = x[j]; s += v * v; }
    #pragma unroll
    for (int o = 16; o; o >>= 1) s += __shfl_xor_sync(0xffffffffu, s, o);
    __shared__ float ws[4];
    if ((threadIdx.x & 31) == 0) ws[threadIdx.x >> 5] = s;
    __syncthreads();
    float rs = rsqrtf((ws[0] + ws[1] + ws[2] + ws[3]) / (float)DM_ + 1e-5f);
    __half* dst = A6 + (size_t)row * (3 * DM_);
    for (int p = threadIdx.x; p < DM_ / 2; p += 128) {
        int k = p * 2;
        packA_pair(x[k] * rs * w[k], x[k + 1] * rs * w[k + 1],
                   reinterpret_cast<uint32_t*>(dst + p * 6));
    }
}

// ---------------- Depthwise conv (K=4) + SiLU, fused with A split ----------------
__global__ void conv_silu_split_kernel(const float* __restrict__ xz,
                                       const float* __restrict__ cw,
                                       const float* __restrict__ cb,
                                       float* __restrict__ xc,
                                       __half* __restrict__ A6)
{
    int idx = blockIdx.x * blockDim.x + threadIdx.x;
    if (idx >= B_ * LQ_ * (DI_ / 2)) return;
    int d2 = idx & 511;
    int l  = (idx >> 9) & 511;
    int b  = idx >> 18;
    int d  = d2 * 2;
    const float* base = xz + (size_t)b * LQ_ * 2 * DI_ + d;
    float s0 = cb[d], s1 = cb[d + 1];
    #pragma unroll
    for (int k = 0; k < 4; k++) {
        int ll = l - 3 + k;
        if (ll >= 0) {
            float2 v = *reinterpret_cast<const float2*>(base + (size_t)ll * (2 * DI_));
            s0 = fmaf(cw[d * 4 + k], v.x, s0);
            s1 = fmaf(cw[(d + 1) * 4 + k], v.y, s1);
        }
    }
    float y0 = s0 / (1.f + __expf(-s0));
    float y1 = s1 / (1.f + __expf(-s1));
    int row = b * LQ_ + l;
    *reinterpret_cast<float2*>(xc + (size_t)row * DI_ + d) = make_float2(y0, y1);
    packA_pair(y0, y1, reinterpret_cast<uint32_t*>(A6 + (size_t)row * (3 * DI_) + d2 * 6));
}

// ---------------- Selective scan: 4 threads per (b,d), fused with ys split ----------------
__global__ void scan_kernel(const float* __restrict__ delta,
                            const float* __restrict__ xc,
                            const float* __restrict__ dbl,
                            const float* __restrict__ xz,
                            const float* __restrict__ A_log,
                            const float* __restrict__ Dskip,
                            __half* __restrict__ A6)
{
    int t = blockIdx.x * blockDim.x + threadIdx.x;   // 32768 threads
    int ch = t >> 2, sub = t & 3;
    int d = ch & (DI_ - 1);
    int b = ch >> 10;
    int n0 = sub * 4;

    float A[4], h[4];
    #pragma unroll
    for (int j = 0; j < 4; j++) { A[j] = -__expf(A_log[d * DS_ + n0 + j]); h[j] = 0.f; }
    float Dv = Dskip[d];
    bool writer = ((t & 7) == 0);
    int d2 = d >> 1;

    for (int l = 0; l < LQ_; l++) {
        int row = b * LQ_ + l;
        float dt = delta[(size_t)row * DI_ + d];
        float u  = xc[(size_t)row * DI_ + d];
        float du = dt * u;
        float4 Bv = *reinterpret_cast<const float4*>(dbl + (size_t)row * 64 + DTR_ + n0);
        float4 Cv = *reinterpret_cast<const float4*>(dbl + (size_t)row * 64 + DTR_ + DS_ + n0);
        float y;
        {
            float dA0 = __expf(dt * A[0]); h[0] = fmaf(dA0, h[0], du * Bv.x);
            float dA1 = __expf(dt * A[1]); h[1] = fmaf(dA1, h[1], du * Bv.y);
            float dA2 = __expf(dt * A[2]); h[2] = fmaf(dA2, h[2], du * Bv.z);
            float dA3 = __expf(dt * A[3]); h[3] = fmaf(dA3, h[3], du * Bv.w);
            y = h[0] * Cv.x + h[1] * Cv.y + h[2] * Cv.z + h[3] * Cv.w;
        }
        y += __shfl_xor_sync(0xffffffffu, y, 1);
        y += __shfl_xor_sync(0xffffffffu, y, 2);
        float z = xz[(size_t)row * (2 * DI_) + DI_ + d];
        float sz = z / (1.f + __expf(-z));
        float yv = (y + u * Dv) * sz;
        float yo = __shfl_xor_sync(0xffffffffu, yv, 4);
        if (writer) {
            packA_pair(yv, yo,
                reinterpret_cast<uint32_t*>(A6 + (size_t)row * (3 * DI_) + d2 * 6));
        }
    }
}

// ---------------- Attention (fp32 SIMT) ----------------
__global__ void attn_kernel(const float* __restrict__ Q,
                            const float* __restrict__ Kb,
                            const float* __restrict__ Vb,
                            float* __restrict__ O)
{
    const int qt = blockIdx.x * 16;
    const int h  = blockIdx.y;
    const int b  = blockIdx.z;
    __shared__ float Qs[16][128];
    __shared__ float Ks[32][128];
    __shared__ float S[16][256];
    const int tid = threadIdx.x;

    #pragma unroll
    for (int j = 0; j < 8; j++) {
        int idx = tid + j * 256;
        int qi = idx >> 7, dd = idx & 127;
        Qs[qi][dd] = Q[((size_t)(b * LQ_ + qt + qi)) * DM_ + h * DH_ + dd];
    }
    const float scale = 0.08838834764831845f;
    for (int kc = 0; kc < 8; kc++) {
        #pragma unroll
        for (int j = 0; j < 16; j++) {
            int idx = tid + j * 256;
            int ki = idx >> 7, dd = idx & 127;
            Ks[ki][dd] = Kb[((size_t)(b * LK_ + kc * 32 + ki)) * DM_ + h * DH_ + dd];
        }
        __syncthreads();
        #pragma unroll
        for (int j = 0; j < 2; j++) {
            int p = tid + j * 256;
            int qi = p >> 5, ki = p & 31;
            float s = 0.f;
            #pragma unroll 4
            for (int dd = 0; dd < 128; dd++) s = fmaf(Qs[qi][dd], Ks[ki][dd], s);
            S[qi][kc * 32 + ki] = s * scale;
        }
        __syncthreads();
    }
    {
        int warp = tid >> 5, lane = tid & 31;
        for (int r = warp * 2; r < warp * 2 + 2; r++) {
            float m = -1e30f;
            #pragma unroll
            for (int j = lane; j < 256; j += 32) m = fmaxf(m, S[r][j]);
            #pragma unroll
            for (int o = 16; o; o >>= 1) m = fmaxf(m, __shfl_xor_sync(0xffffffffu, m, o));
            float sum = 0.f;
            #pragma unroll
            for (int j = lane; j < 256; j += 32) {
                float e = __expf(S[r][j] - m);
                S[r][j] = e; sum += e;
            }
            #pragma unroll
            for (int o = 16; o; o >>= 1) sum += __shfl_xor_sync(0xffffffffu, sum, o);
            float inv = 1.f / sum;
            #pragma unroll
            for (int j = lane; j < 256; j += 32) S[r][j] *= inv;
        }
    }
    __syncthreads();
    {
        int dd = tid & 127, qg = tid >> 7;
        float acc[8];
        #pragma unroll
        for (int r = 0; r < 8; r++) acc[r] = 0.f;
        for (int k = 0; k < 256; k++) {
            float v = Vb[((size_t)(b * LK_ + k)) * DM_ + h * DH_ + dd];
            #pragma unroll
            for (int r = 0; r < 8; r++) acc[r] = fmaf(S[qg * 8 + r][k], v, acc[r]);
        }
        #pragma unroll
        for (int r = 0; r < 8; r++) {
            int qi = qg * 8 + r;
            O[((size_t)(b * LQ_ + qt + qi)) * DM_ + h * DH_ + dd] = acc[r];
        }
    }
}

// ---------------- Small fp32 GEMM for the N=6 head ----------------
__global__ void head_gemm_kernel(const float* __restrict__ A,
                                 const float* __restrict__ W,
                                 const float* __restrict__ bias,
                                 float* __restrict__ C, int M, int N, int K)
{
    __shared__ __align__(16) float As[16][64];
    __shared__ float Ws[16][8];
    const int bm = blockIdx.y * 64;
    const int tid = threadIdx.x;
    const int tx = tid & 15, ty = tid >> 4;
    float acc[4] = {0.f, 0.f, 0.f, 0.f};
    for (int k0 = 0; k0 < K; k0 += 16) {
        #pragma unroll
        for (int j = 0; j < 4; j++) {
            int idx = tid + j * 256;
            int m = idx >> 4, k = idx & 15;
            As[k][m] = A[(size_t)(bm + m) * K + (k0 + k)];
        }
        if (tid < 16 * 8) {
            int k = tid >> 3, n = tid & 7;
            Ws[k][n] = (n < N) ? W[(size_t)(k0 + k) * N + n] : 0.f;
        }
        __syncthreads();
        if (tx < 8) {
            #pragma unroll
            for (int k = 0; k < 16; k++) {
                float wv = Ws[k][tx];
                #pragma unroll
                for (int r = 0; r < 4; r++) acc[r] = fmaf(As[k][ty * 4 + r], wv, acc[r]);
            }
        }
        __syncthreads();
    }
    if (tx < N) {
        #pragma unroll
        for (int r = 0; r < 4; r++)
            C[(size_t)(bm + ty * 4 + r) * N + tx] = acc[r] + bias[tx];
    }
}

// ---------------- Argmax ----------------
__global__ void argmax_kernel(const float* __restrict__ probs, float* __restrict__ preds)
{
    int i = blockIdx.x * blockDim.x + threadIdx.x;
    if (i >= ROWS_Q) return;
    const float* p = probs + (size_t)i * NOUT_;
    float best = p[0]; int bi = 0;
    #pragma unroll
    for (int j = 1; j < NOUT_; j++) if (p[j] > best) { best = p[j]; bi = j; }
    preds[i] = (float)bi;
}

// ---------------- Host launch ----------------
#define SMEM_PIPE_128 (3 * (128 + 128) * 128)   // 98304
#define SMEM_PIPE_64N (3 * (128 + 64) * 128)    // 73728 (128x64 atomic)
#define SMEM_PIPE_64M (3 * (64 + 128) * 128)    // 73728 (64x128)

extern "C" void kernel_launch(void* const* d_in, const int* in_sizes, int n_in,
                              void* d_out, int out_size)
{
    const float* agent   = (const float*)d_in[0];
    const float* lane    = (const float*)d_in[1];
    const float* lane_W  = (const float*)d_in[2];
    const float* lane_b  = (const float*)d_in[3];
    const float* norm_w  = (const float*)d_in[4];
    const float* inpW    = (const float*)d_in[5];
    const float* convw   = (const float*)d_in[6];
    const float* convb   = (const float*)d_in[7];
    const float* xprW    = (const float*)d_in[8];
    const float* dtW     = (const float*)d_in[9];
    const float* dtb     = (const float*)d_in[10];
    const float* A_log   = (const float*)d_in[11];
    const float* Dskip   = (const float*)d_in[12];
    const float* outW    = (const float*)d_in[13];
    const float* fnw     = (const float*)d_in[14];
    const float* Wq      = (const float*)d_in[15];
    const float* Wk      = (const float*)d_in[16];
    const float* Wv      = (const float*)d_in[17];
    const float* Wo      = (const float*)d_in[18];
    const float* bq      = (const float*)d_in[19];
    const float* bk      = (const float*)d_in[20];
    const float* bv      = (const float*)d_in[21];
    const float* bo      = (const float*)d_in[22];
    const float* linW    = (const float*)d_in[23];
    const float* linb    = (const float*)d_in[24];
    const float* loutW   = (const float*)d_in[25];
    const float* loutb   = (const float*)d_in[26];

    float *px, *ph, *pxz, *pxc, *pdbl, *pdlt, *pq, *pk, *pv, *patt;
    __half *pA6, *pAag, *pB;
    cudaGetSymbolAddress((void**)&px,   g_x);
    cudaGetSymbolAddress((void**)&ph,   g_h);
    cudaGetSymbolAddress((void**)&pxz,  g_xz);
    cudaGetSymbolAddress((void**)&pxc,  g_xc);
    cudaGetSymbolAddress((void**)&pdbl, g_dbl);
    cudaGetSymbolAddress((void**)&pdlt, g_dlt);
    cudaGetSymbolAddress((void**)&pq,   g_q);
    cudaGetSymbolAddress((void**)&pk,   g_k);
    cudaGetSymbolAddress((void**)&pv,   g_v);
    cudaGetSymbolAddress((void**)&patt, g_att);
    cudaGetSymbolAddress((void**)&pA6,  g_A6);
    cudaGetSymbolAddress((void**)&pAag, g_Aag);
    cudaGetSymbolAddress((void**)&pB,   g_B6all);

    cudaFuncSetAttribute(mma_gemm_pipe<128,128,false,false>,
                         cudaFuncAttributeMaxDynamicSharedMemorySize, SMEM_PIPE_128);
    cudaFuncSetAttribute(mma_gemm_pipe<128,64,false,true>,
                         cudaFuncAttributeMaxDynamicSharedMemorySize, SMEM_PIPE_64N);
    cudaFuncSetAttribute(mma_gemm_pipe<64,128,false,false>,
                         cudaFuncAttributeMaxDynamicSharedMemorySize, SMEM_PIPE_64M);
    cudaFuncSetAttribute(mma_gemm_pipe<64,128,true,false>,
                         cudaFuncAttributeMaxDynamicSharedMemorySize, SMEM_PIPE_64M);

    float* probs = (float*)d_out;

    // ---- build weight-split descriptor table ----
    SplitDescs da;
    __half* bLane;  __half* bIn[4]; __half* bXp[4]; __half* bDt[4]; __half* bOut[4];
    __half* bQ; __half* bK; __half* bV; __half* bO; __half* bLin;
    {
        int di = 0; size_t off = 0; int tiles = 0;
        auto add = [&](const float* W, int K, int N, __half** save) {
            da.W[di] = W; da.dst[di] = pB + off; da.K[di] = K; da.N[di] = N;
            da.tileBase[di] = tiles;
            *save = pB + off;
            off += (size_t)N * 3 * K;
            tiles += (K >> 5) * (N >> 5);
            di++;
        };
        add(lane_W, 128, DM_, &bLane);
        for (int i = 0; i < 4; i++) add(inpW + (size_t)i * DM_ * 2 * DI_, DM_, 2 * DI_, &bIn[i]);
        for (int i = 0; i < 4; i++) add(xprW + (size_t)i * DI_ * 64,      DI_, 64,      &bXp[i]);
        for (int i = 0; i < 4; i++) add(dtW  + (size_t)i * DTR_ * DI_,    DTR_, DI_,    &bDt[i]);
        for (int i = 0; i < 4; i++) add(outW + (size_t)i * DI_ * DM_,     DI_, DM_,     &bOut[i]);
        add(Wq,  DM_, DM_, &bQ);
        add(Wk,  DM_, DM_, &bK);
        add(Wv,  DM_, DM_, &bV);
        add(Wo,  DM_, DM_, &bO);
        add(linW, DM_, DM_, &bLin);
        // total tiles = 7872, total halves ~24.2M
        splitB_all<<<tiles, dim3(32, 8)>>>(da);
    }
    // agent activation split (constant input) up front
    splitA_kernel<<<(ROWS_K * 256 + 255) / 256, 256>>>(agent, DM_, 8, ROWS_K * 256, pAag);

    // ---- lane_in: x = lane @ lane_W + lane_b (Keff=384), grid 256 ----
    splitA_kernel<<<(ROWS_Q * 64 + 255) / 256, 256>>>(lane, 128, 6, ROWS_Q * 64, pA6);
    mma_gemm_pipe<64,128,false,false><<<dim3(DM_/128, ROWS_Q/64), 256, SMEM_PIPE_64M>>>(pA6, bLane, lane_b, px, DM_, 3*128);

    for (int i = 0; i < NBLK_; i++) {
        rmsnorm_split_kernel<<<ROWS_Q, 128>>>(px, norm_w + i * DM_, pA6);
        // in_proj: Keff=1536, N=2048, grid 512 (BM=128)
        mma_gemm_pipe<128,128,false,false><<<dim3(2*DI_/128, ROWS_Q/128), 256, SMEM_PIPE_128>>>(pA6, bIn[i], nullptr, pxz, 2*DI_, 3*DM_);
        conv_silu_split_kernel<<<(B_*LQ_*DI_/2 + 255) / 256, 256>>>(pxz,
            convw + (size_t)i * DI_ * 4, convb + (size_t)i * DI_, pxc, pA6);
        // x_proj: Keff=3072, N=64, split-K=4 atomic, grid 128
        cudaMemsetAsync(pdbl, 0, (size_t)ROWS_Q * 64 * sizeof(float));
        mma_gemm_pipe<128,64,false,true><<<dim3(1, ROWS_Q/128, 4), 256, SMEM_PIPE_64N>>>(pA6, bXp[i], nullptr, pdbl, 64, 3*DI_);
        // dt_proj (softplus): Keff=96, N=1024 (non-pipelined)
        splitA_kernel<<<(ROWS_Q * 16 + 255) / 256, 256>>>(pdbl, 64, 4, ROWS_Q * 16, pA6);
        mma_gemm<128,128,2,4,false,1,false><<<dim3(DI_/128, ROWS_Q/128), 256>>>(pA6, bDt[i], dtb + (size_t)i * DI_, pdlt, DI_, 3*DTR_);
        // scan -> A6 (out_proj A)
        scan_kernel<<<128, 256>>>(pdlt, pxc, pdbl, pxz,
            A_log + (size_t)i * DI_ * DS_, Dskip + (size_t)i * DI_, pA6);
        // out_proj (+= residual): Keff=3072, N=512, grid 256 (BM=64)
        mma_gemm_pipe<64,128,true,false><<<dim3(DM_/128, ROWS_Q/64), 256, SMEM_PIPE_64M>>>(pA6, bOut[i], nullptr, px, DM_, 3*DI_);
    }

    rmsnorm_split_kernel<<<ROWS_Q, 128>>>(px, fnw, pA6);
    mma_gemm_pipe<64,128,false,false><<<dim3(DM_/128, ROWS_Q/64), 256, SMEM_PIPE_64M>>>(pA6, bQ, bq, pq, DM_, 3*DM_);

    mma_gemm_pipe<64,128,false,false><<<dim3(DM_/128, ROWS_K/64), 256, SMEM_PIPE_64M>>>(pAag, bK, bk, pk, DM_, 3*DM_);
    mma_gemm_pipe<64,128,false,false><<<dim3(DM_/128, ROWS_K/64), 256, SMEM_PIPE_64M>>>(pAag, bV, bv, pv, DM_, 3*DM_);

    attn_kernel<<<dim3(LQ_/16, NHEAD_, B_), 256>>>(pq, pk, pv, patt);

    splitA_kernel<<<(ROWS_Q * 256 + 255) / 256, 256>>>(patt, DM_, 8, ROWS_Q * 256, pA6);
    mma_gemm_pipe<64,128,false,false><<<dim3(DM_/128, ROWS_Q/64), 256, SMEM_PIPE_64M>>>(pA6, bO, bo, px, DM_, 3*DM_);

    splitA_kernel<<<(ROWS_Q * 256 + 255) / 256, 256>>>(px, DM_, 8, ROWS_Q * 256, pA6);
    mma_gemm_pipe<64,128,false,false><<<dim3(DM_/128, ROWS_Q/64), 256, SMEM_PIPE_64M>>>(pA6, bLin, linb, ph, DM_, 3*DM_);

    head_gemm_kernel<<<dim3(1, ROWS_Q/64), 256>>>(ph, loutW, loutb, probs, ROWS_Q, NOUT_, DM_);
    if (out_size >= ROWS_Q * NOUT_ + ROWS_Q) {
        argmax_kernel<<<(ROWS_Q + 255) / 256, 256>>>(probs, probs + ROWS_Q * NOUT_);
    }
}